// round 2
// baseline (speedup 1.0000x reference)
#include <cuda_runtime.h>
#include <math.h>

#define TT 1024
#define CC 2048
#define HH 32
#define ND 64
#define TC (TT*CC)
#define EPSGN 0.00064f

// ---------------------------------------------------------------------------
// Scratch: one __device__ array (no runtime allocs allowed)
// ---------------------------------------------------------------------------
__device__ float g_scratch[16ull*TC + 2ull*TT*128 + (size_t)TT*64 + 4ull*TT*16];

#define O_DXP   ((size_t)0*TC)
#define O_XXX   ((size_t)1*TC)
#define O_XRG   ((size_t)2*TC)
#define O_XWA   ((size_t)3*TC)
#define O_XK    ((size_t)4*TC)
#define O_XV    ((size_t)5*TC)
#define O_R     ((size_t)6*TC)
#define O_KRAW  ((size_t)7*TC)
#define O_V     ((size_t)8*TC)
#define O_DEC   ((size_t)9*TC)
#define O_A     ((size_t)10*TC)
#define O_KK    ((size_t)11*TC)
#define O_K     ((size_t)12*TC)
#define O_G     ((size_t)13*TC)
#define O_Y     ((size_t)14*TC)
#define O_YM    ((size_t)15*TC)
#define O_HMIX  ((size_t)16*TC)
#define O_GH    (O_HMIX + (size_t)TT*128)
#define O_HD    (O_GH   + (size_t)TT*128)
#define O_HAAA  (O_HD   + (size_t)TT*64)
#define O_HMA   (O_HAAA + (size_t)TT*16)
#define O_HMK   (O_HMA  + (size_t)TT*16)
#define O_HKKK  (O_HMK  + (size_t)TT*16)

// ---------------------------------------------------------------------------
// token shift: dxp = x[t-1]-x[t]; xxx = x + dxp * time_maa_x
// ---------------------------------------------------------------------------
__global__ void k_tokshift(const float* __restrict__ x, const float* __restrict__ maa_x,
                           float* __restrict__ dxp, float* __restrict__ xxx) {
    int idx = blockIdx.x * blockDim.x + threadIdx.x;
    if (idx >= TC) return;
    int t = idx >> 11;
    int c = idx & (CC - 1);
    float xv = x[idx];
    float pv = (t > 0) ? x[idx - CC] : 0.0f;
    float dx = pv - xv;
    dxp[idx] = dx;
    xxx[idx] = fmaf(dx, maa_x[c], xv);
}

// ---------------------------------------------------------------------------
// narrow GEMM: out[T,NN] = act(A[T,CC] @ W[CC,NN]); NN in {16,64,128}
// ---------------------------------------------------------------------------
template <int NN, bool ACT>
__global__ void k_gemm_small(const float* __restrict__ A, const float* __restrict__ W,
                             float* __restrict__ out) {
    constexpr int G   = 128 / NN;
    constexpr int RPT = 4;
    constexpr int RT  = G * RPT;
    constexpr int KC  = 64;
    __shared__ float As[RT][KC + 1];
    const int n  = threadIdx.x % NN;
    const int g  = threadIdx.x / NN;
    const int r0 = blockIdx.x * RT;
    float acc[RPT];
#pragma unroll
    for (int i = 0; i < RPT; i++) acc[i] = 0.f;
    for (int kc = 0; kc < CC; kc += KC) {
        __syncthreads();
        for (int i = threadIdx.x; i < RT * KC; i += 128) {
            int rr = i / KC, ck = i % KC;
            As[rr][ck] = A[(size_t)(r0 + rr) * CC + kc + ck];
        }
        __syncthreads();
#pragma unroll 4
        for (int k = 0; k < KC; k++) {
            float wv = W[(size_t)(kc + k) * NN + n];
#pragma unroll
            for (int i = 0; i < RPT; i++)
                acc[i] = fmaf(As[g * RPT + i][k], wv, acc[i]);
        }
    }
#pragma unroll
    for (int i = 0; i < RPT; i++) {
        float v = acc[i];
        if (ACT) v = tanhf(v);
        out[(size_t)(r0 + g * RPT + i) * NN + n] = v;
    }
}

// ---------------------------------------------------------------------------
// mix apply: X_f = x + dxp*(tm_f + hmix[:, f*32:(f+1)*32] @ maa_w2[f])
// grid (CC/128, TT/8, 4), block 128
// ---------------------------------------------------------------------------
__global__ void k_mix_apply(const float* __restrict__ x, const float* __restrict__ dxp,
                            const float* __restrict__ hmix, const float* __restrict__ w2full,
                            const float* __restrict__ tm0, const float* __restrict__ tm1,
                            const float* __restrict__ tm2, const float* __restrict__ tm3,
                            float* __restrict__ o0, float* __restrict__ o1,
                            float* __restrict__ o2, float* __restrict__ o3) {
    const int f  = blockIdx.z;
    const int t0 = blockIdx.y * 8;
    const int c  = blockIdx.x * 128 + threadIdx.x;
    __shared__ float hm[8][32];
    for (int i = threadIdx.x; i < 8 * 32; i += 128) {
        int tt = i >> 5, d = i & 31;
        hm[tt][d] = hmix[(size_t)(t0 + tt) * 128 + f * 32 + d];
    }
    __syncthreads();
    const float* w2 = w2full + (size_t)f * 32 * CC;
    float acc[8];
#pragma unroll
    for (int i = 0; i < 8; i++) acc[i] = 0.f;
#pragma unroll 4
    for (int d = 0; d < 32; d++) {
        float wv = w2[(size_t)d * CC + c];
#pragma unroll
        for (int tt = 0; tt < 8; tt++) acc[tt] = fmaf(hm[tt][d], wv, acc[tt]);
    }
    const float* tm  = (f == 0) ? tm0 : (f == 1) ? tm1 : (f == 2) ? tm2 : tm3;
    float*       out = (f == 0) ? o0  : (f == 1) ? o1  : (f == 2) ? o2  : o3;
    float tmv = tm[c];
#pragma unroll
    for (int tt = 0; tt < 8; tt++) {
        size_t idx = (size_t)(t0 + tt) * CC + c;
        out[idx] = fmaf(dxp[idx], tmv + acc[tt], x[idx]);
    }
}

// ---------------------------------------------------------------------------
// big SGEMM: C = A[M,K] @ B[K,N2]; 128x128x16 tiles, 8x8/thread
// ---------------------------------------------------------------------------
#define BM 128
#define BN 128
#define BK 16
__global__ __launch_bounds__(256) void k_sgemm(const float* __restrict__ A,
                                               const float* __restrict__ B,
                                               float* __restrict__ Co,
                                               int M, int N2, int K) {
    __shared__ float As[BK][BM];
    __shared__ float Bs[BK][BN];
    const int tid = threadIdx.x;
    const int bm  = blockIdx.y * BM;
    const int bn  = blockIdx.x * BN;
    const int ty  = tid >> 4;
    const int tx  = tid & 15;
    const int ar  = tid >> 2;
    const int acq = tid & 3;
    const int br  = tid >> 5;
    const int bc4 = tid & 31;

    const float* aPtr0 = A + (size_t)(bm + ar) * K + acq * 4;
    const float* aPtr1 = aPtr0 + (size_t)64 * K;
    const float* bPtr0 = B + (size_t)br * N2 + bn + bc4 * 4;
    const float* bPtr1 = bPtr0 + (size_t)8 * N2;

    float acc[8][8];
#pragma unroll
    for (int i = 0; i < 8; i++)
#pragma unroll
        for (int j = 0; j < 8; j++) acc[i][j] = 0.f;

    const int KT = K / BK;
    float4 a0 = *(const float4*)(aPtr0);
    float4 a1 = *(const float4*)(aPtr1);
    float4 b0 = *(const float4*)(bPtr0);
    float4 b1 = *(const float4*)(bPtr1);

    for (int kt = 0; kt < KT; kt++) {
        As[acq * 4 + 0][ar] = a0.x;  As[acq * 4 + 1][ar] = a0.y;
        As[acq * 4 + 2][ar] = a0.z;  As[acq * 4 + 3][ar] = a0.w;
        As[acq * 4 + 0][64 + ar] = a1.x;  As[acq * 4 + 1][64 + ar] = a1.y;
        As[acq * 4 + 2][64 + ar] = a1.z;  As[acq * 4 + 3][64 + ar] = a1.w;
        *(float4*)&Bs[br][bc4 * 4]     = b0;
        *(float4*)&Bs[8 + br][bc4 * 4] = b1;
        __syncthreads();
        if (kt + 1 < KT) {
            a0 = *(const float4*)(aPtr0 + (size_t)(kt + 1) * BK);
            a1 = *(const float4*)(aPtr1 + (size_t)(kt + 1) * BK);
            b0 = *(const float4*)(bPtr0 + (size_t)(kt + 1) * BK * N2);
            b1 = *(const float4*)(bPtr1 + (size_t)(kt + 1) * BK * N2);
        }
#pragma unroll 4
        for (int k = 0; k < BK; k++) {
            float xa[8], xb[8];
            *(float4*)&xa[0] = *(const float4*)&As[k][ty * 8];
            *(float4*)&xa[4] = *(const float4*)&As[k][ty * 8 + 4];
            *(float4*)&xb[0] = *(const float4*)&Bs[k][tx * 8];
            *(float4*)&xb[4] = *(const float4*)&Bs[k][tx * 8 + 4];
#pragma unroll
            for (int i = 0; i < 8; i++)
#pragma unroll
                for (int j = 0; j < 8; j++)
                    acc[i][j] = fmaf(xa[i], xb[j], acc[i][j]);
        }
        __syncthreads();
    }
#pragma unroll
    for (int i = 0; i < 8; i++) {
        int row = bm + ty * 8 + i;
        *(float4*)&Co[(size_t)row * N2 + bn + tx * 8]     =
            make_float4(acc[i][0], acc[i][1], acc[i][2], acc[i][3]);
        *(float4*)&Co[(size_t)row * N2 + bn + tx * 8 + 4] =
            make_float4(acc[i][4], acc[i][5], acc[i][6], acc[i][7]);
    }
}

// ---------------------------------------------------------------------------
// stage 2: decay/a/ma/mk/kk/k/gate fully fused. grid TT/8, block 256.
// ---------------------------------------------------------------------------
__global__ __launch_bounds__(256) void k_stage2(
    const float* __restrict__ kraw_in,
    const float* __restrict__ hd,   const float* __restrict__ haaa,
    const float* __restrict__ hma,  const float* __restrict__ hmk,
    const float* __restrict__ hkkk, const float* __restrict__ gh,
    const float* __restrict__ td,   const float* __restrict__ dw2,
    const float* __restrict__ taa,  const float* __restrict__ aw2,
    const float* __restrict__ tmisca, const float* __restrict__ maw2,
    const float* __restrict__ tmisck, const float* __restrict__ mkw2,
    const float* __restrict__ kkkw2,  const float* __restrict__ gw2,
    float* __restrict__ decout, float* __restrict__ aout,
    float* __restrict__ kkout,  float* __restrict__ kout, float* __restrict__ gout) {
    const int t0  = blockIdx.x * 8;
    const int tid = threadIdx.x;
    __shared__ float shd[8][64];
    __shared__ float sh16[4][8][16];
    __shared__ float shg[8][128];
    for (int i = tid; i < 8 * 64; i += 256)
        shd[i >> 6][i & 63] = hd[(size_t)(t0 + (i >> 6)) * 64 + (i & 63)];
    for (int i = tid; i < 8 * 16; i += 256) {
        int r = i >> 4, j = i & 15;
        sh16[0][r][j] = haaa[(size_t)(t0 + r) * 16 + j];
        sh16[1][r][j] = hma [(size_t)(t0 + r) * 16 + j];
        sh16[2][r][j] = hmk [(size_t)(t0 + r) * 16 + j];
        sh16[3][r][j] = hkkk[(size_t)(t0 + r) * 16 + j];
    }
    for (int i = tid; i < 8 * 128; i += 256)
        shg[i >> 7][i & 127] = gh[(size_t)(t0 + (i >> 7)) * 128 + (i & 127)];
    __syncthreads();

    for (int c = tid; c < CC; c += 256) {
        float ud[8], ua[8], uma[8], umk[8], ukk[8], ug[8];
#pragma unroll
        for (int r = 0; r < 8; r++) { ud[r]=0.f; ua[r]=0.f; uma[r]=0.f; umk[r]=0.f; ukk[r]=0.f; ug[r]=0.f; }
#pragma unroll 4
        for (int j = 0; j < 64; j++) {
            float w = dw2[(size_t)j * CC + c];
#pragma unroll
            for (int r = 0; r < 8; r++) ud[r] = fmaf(shd[r][j], w, ud[r]);
        }
#pragma unroll 2
        for (int j = 0; j < 16; j++) {
            float w1 = aw2[(size_t)j * CC + c],  w2v = maw2[(size_t)j * CC + c];
            float w3 = mkw2[(size_t)j * CC + c], w4  = kkkw2[(size_t)j * CC + c];
#pragma unroll
            for (int r = 0; r < 8; r++) {
                ua[r]  = fmaf(sh16[0][r][j], w1,  ua[r]);
                uma[r] = fmaf(sh16[1][r][j], w2v, uma[r]);
                umk[r] = fmaf(sh16[2][r][j], w3,  umk[r]);
                ukk[r] = fmaf(sh16[3][r][j], w4,  ukk[r]);
            }
        }
#pragma unroll 4
        for (int j = 0; j < 128; j++) {
            float w = gw2[(size_t)j * CC + c];
#pragma unroll
            for (int r = 0; r < 8; r++) ug[r] = fmaf(shg[r][j], w, ug[r]);
        }
        float tdv = td[c], taav = taa[c], tmav = tmisca[c], tmkv = tmisck[c];
#pragma unroll
        for (int r = 0; r < 8; r++) {
            size_t idx = (size_t)(t0 + r) * CC + c;
            float z  = tdv + ud[r];
            float wv = -(fmaxf(-z, 0.f) + log1pf(expf(-fabsf(z)))) - 0.5f;  // -softplus(-z)-0.5
            decout[idx] = expf(wv);
            float av  = 1.f / (1.f + expf(-(taav + ua[r])));
            aout[idx] = av;
            float mav = 1.f / (1.f + expf(-(tmav + uma[r])));
            float mkv = 1.f / (1.f + expf(-(tmkv + umk[r])));
            float kr  = kraw_in[idx];
            kkout[idx] = kr + ukk[r];
            float km = kr * (mav + av * (1.f - mav));
            km *= expf(fminf(wv * mkv, 0.f));
            kout[idx] = km;
            gout[idx] = ug[r];
        }
    }
}

// ---------------------------------------------------------------------------
// kk per-head L2 normalization. grid TT, block 256 (8 channels / thread)
// ---------------------------------------------------------------------------
__global__ void k_kknorm(float* __restrict__ kk) {
    const int t    = blockIdx.x;
    const int tid  = threadIdx.x;
    const size_t base = (size_t)t * CC + tid * 8;
    float4 a = *(float4*)&kk[base];
    float4 b = *(float4*)&kk[base + 4];
    float ss = a.x*a.x + a.y*a.y + a.z*a.z + a.w*a.w
             + b.x*b.x + b.y*b.y + b.z*b.z + b.w*b.w;
    ss += __shfl_xor_sync(0xffffffffu, ss, 1);
    ss += __shfl_xor_sync(0xffffffffu, ss, 2);
    ss += __shfl_xor_sync(0xffffffffu, ss, 4);
    float inv = 1.f / fmaxf(sqrtf(ss), 1e-12f);
    a.x *= inv; a.y *= inv; a.z *= inv; a.w *= inv;
    b.x *= inv; b.y *= inv; b.z *= inv; b.w *= inv;
    *(float4*)&kk[base]     = a;
    *(float4*)&kk[base + 4] = b;
}

// ---------------------------------------------------------------------------
// WKV7. grid (32 heads, 4 row-splits), block 256.
// thread (il 0..15 row, cg 0..15 col-group); state float4 in registers.
// ---------------------------------------------------------------------------
__global__ __launch_bounds__(256) void k_wkv(
    const float* __restrict__ R, const float* __restrict__ Dec,
    const float* __restrict__ K, const float* __restrict__ Kk,
    const float* __restrict__ Asig, const float* __restrict__ V,
    float* __restrict__ Y) {
    const int h   = blockIdx.x;
    const int rb  = blockIdx.y;
    const int tid = threadIdx.x;
    const int il  = tid >> 4;
    const int cg  = tid & 15;
    const int i   = rb * 16 + il;
    const int colbase = h * 64 + cg * 4;
    const int rowidx  = h * 64 + i;

    float4 s = make_float4(0.f, 0.f, 0.f, 0.f);
    for (int t = 0; t < TT; t++) {
        const size_t ob = (size_t)t * CC;
        float4 kkv = *(const float4*)&Kk[ob + colbase];
        float4 dv  = *(const float4*)&Dec[ob + colbase];
        float4 kv  = *(const float4*)&K[ob + colbase];
        float4 rv  = *(const float4*)&R[ob + colbase];
        float4 av  = *(const float4*)&Asig[ob + colbase];
        float  vi  = V[ob + rowidx];

        // sa_i = sum_j S[i,j] * (-kk_j)
        float sa = s.x*kkv.x + s.y*kkv.y + s.z*kkv.z + s.w*kkv.w;
        sa += __shfl_xor_sync(0xffffffffu, sa, 1);
        sa += __shfl_xor_sync(0xffffffffu, sa, 2);
        sa += __shfl_xor_sync(0xffffffffu, sa, 4);
        sa += __shfl_xor_sync(0xffffffffu, sa, 8);
        sa = -sa;

        // b_j = kk_j * a_j ; S = S*dec + sa*b + v_i*k
        s.x = fmaf(vi, kv.x, fmaf(sa, kkv.x*av.x, s.x*dv.x));
        s.y = fmaf(vi, kv.y, fmaf(sa, kkv.y*av.y, s.y*dv.y));
        s.z = fmaf(vi, kv.z, fmaf(sa, kkv.z*av.z, s.z*dv.z));
        s.w = fmaf(vi, kv.w, fmaf(sa, kkv.w*av.w, s.w*dv.w));

        float o = s.x*rv.x + s.y*rv.y + s.z*rv.z + s.w*rv.w;
        o += __shfl_xor_sync(0xffffffffu, o, 1);
        o += __shfl_xor_sync(0xffffffffu, o, 2);
        o += __shfl_xor_sync(0xffffffffu, o, 4);
        o += __shfl_xor_sync(0xffffffffu, o, 8);
        if (cg == 0) Y[ob + rowidx] = o;
    }
}

// ---------------------------------------------------------------------------
// groupnorm + faaaa bonus + gate multiply. grid TT, block 512 (4 ch/thread)
// ---------------------------------------------------------------------------
__global__ __launch_bounds__(512) void k_gn(
    const float* __restrict__ Yin, const float* __restrict__ R,
    const float* __restrict__ K,   const float* __restrict__ V,
    const float* __restrict__ G,   const float* __restrict__ faaaa,
    const float* __restrict__ lnw, const float* __restrict__ lnb,
    float* __restrict__ Yout) {
    const int t   = blockIdx.x;
    const int tid = threadIdx.x;
    const int c   = tid * 4;
    const size_t idx = (size_t)t * CC + c;
    float4 y  = *(const float4*)&Yin[idx];
    float4 r4 = *(const float4*)&R[idx];
    float4 k4 = *(const float4*)&K[idx];
    float4 v4 = *(const float4*)&V[idx];
    float4 g4 = *(const float4*)&G[idx];
    float4 f4 = *(const float4*)&faaaa[c];
    float4 w4 = *(const float4*)&lnw[c];
    float4 b4 = *(const float4*)&lnb[c];

    float s1 = y.x + y.y + y.z + y.w;
    float s2 = y.x*y.x + y.y*y.y + y.z*y.z + y.w*y.w;
    float s3 = r4.x*k4.x*f4.x + r4.y*k4.y*f4.y + r4.z*k4.z*f4.z + r4.w*k4.w*f4.w;
#pragma unroll
    for (int m = 1; m <= 8; m <<= 1) {
        s1 += __shfl_xor_sync(0xffffffffu, s1, m);
        s2 += __shfl_xor_sync(0xffffffffu, s2, m);
        s3 += __shfl_xor_sync(0xffffffffu, s3, m);
    }
    float mu  = s1 * (1.f / 64.f);
    float var = s2 * (1.f / 64.f) - mu * mu;
    float rs  = rsqrtf(var + EPSGN);
    float4 o;
    o.x = (fmaf((y.x - mu) * rs, w4.x, b4.x) + s3 * v4.x) * g4.x;
    o.y = (fmaf((y.y - mu) * rs, w4.y, b4.y) + s3 * v4.y) * g4.y;
    o.z = (fmaf((y.z - mu) * rs, w4.z, b4.z) + s3 * v4.z) * g4.z;
    o.w = (fmaf((y.w - mu) * rs, w4.w, b4.w) + s3 * v4.w) * g4.w;
    *(float4*)&Yout[idx] = o;
}

// ---------------------------------------------------------------------------
extern "C" void kernel_launch(void* const* d_in, const int* in_sizes, int n_in,
                              void* d_out, int out_size) {
    const float* x        = (const float*)d_in[0];
    const float* Wq       = (const float*)d_in[1];
    const float* Wk       = (const float*)d_in[2];
    const float* Wv       = (const float*)d_in[3];
    const float* Wo       = (const float*)d_in[4];
    const float* tmx      = (const float*)d_in[5];
    const float* tmrg     = (const float*)d_in[6];
    const float* tmwa     = (const float*)d_in[7];
    const float* tmk      = (const float*)d_in[8];
    const float* tmv      = (const float*)d_in[9];
    const float* maa_w1   = (const float*)d_in[10];
    const float* maa_w2   = (const float*)d_in[11];
    const float* tdecay   = (const float*)d_in[12];
    const float* dw1      = (const float*)d_in[13];
    const float* dw2      = (const float*)d_in[14];
    const float* taaaaa   = (const float*)d_in[15];
    const float* aaa_w1   = (const float*)d_in[16];
    const float* aaa_w2   = (const float*)d_in[17];
    const float* kkk_w1   = (const float*)d_in[18];
    const float* kkk_w2   = (const float*)d_in[19];
    const float* gate_w1  = (const float*)d_in[20];
    const float* gate_w2  = (const float*)d_in[21];
    const float* tmisca   = (const float*)d_in[22];
    const float* ma_w1    = (const float*)d_in[23];
    const float* ma_w2    = (const float*)d_in[24];
    const float* tmisck   = (const float*)d_in[25];
    const float* mk_w1    = (const float*)d_in[26];
    const float* mk_w2    = (const float*)d_in[27];
    const float* faaaa    = (const float*)d_in[28];
    const float* lnw      = (const float*)d_in[29];
    const float* lnb      = (const float*)d_in[30];
    float* out = (float*)d_out;

    float* S = nullptr;
    cudaGetSymbolAddress((void**)&S, g_scratch);

    float* dxp  = S + O_DXP;  float* xxx  = S + O_XXX;
    float* xrg  = S + O_XRG;  float* xwa  = S + O_XWA;
    float* xk   = S + O_XK;   float* xv   = S + O_XV;
    float* R    = S + O_R;    float* Kraw = S + O_KRAW;
    float* V    = S + O_V;    float* Dec  = S + O_DEC;
    float* A    = S + O_A;    float* KK   = S + O_KK;
    float* K    = S + O_K;    float* G    = S + O_G;
    float* Y    = S + O_Y;    float* YM   = S + O_YM;
    float* hmix = S + O_HMIX; float* gh   = S + O_GH;
    float* hd   = S + O_HD;   float* haaa = S + O_HAAA;
    float* hma  = S + O_HMA;  float* hmk  = S + O_HMK;
    float* hkkk = S + O_HKKK;

    k_tokshift<<<TC / 256, 256>>>(x, tmx, dxp, xxx);
    k_gemm_small<128, true><<<TT / 4, 128>>>(xxx, maa_w1, hmix);
    k_mix_apply<<<dim3(CC / 128, TT / 8, 4), 128>>>(x, dxp, hmix, maa_w2,
                                                    tmrg, tmwa, tmk, tmv,
                                                    xrg, xwa, xk, xv);

    dim3 gg(CC / BN, TT / BM);
    k_sgemm<<<gg, 256>>>(xrg, Wq, R,    TT, CC, CC);
    k_sgemm<<<gg, 256>>>(xk,  Wk, Kraw, TT, CC, CC);
    k_sgemm<<<gg, 256>>>(xv,  Wv, V,    TT, CC, CC);

    k_gemm_small<64,  true ><<<TT / 8,  128>>>(xwa, dw1,    hd);
    k_gemm_small<16,  false><<<TT / 32, 128>>>(xwa, aaa_w1, haaa);
    k_gemm_small<16,  false><<<TT / 32, 128>>>(xwa, ma_w1,  hma);
    k_gemm_small<16,  false><<<TT / 32, 128>>>(xk,  mk_w1,  hmk);
    k_gemm_small<16,  true ><<<TT / 32, 128>>>(xk,  kkk_w1, hkkk);
    k_gemm_small<128, true ><<<TT / 4,  128>>>(xrg, gate_w1, gh);

    k_stage2<<<TT / 8, 256>>>(Kraw, hd, haaa, hma, hmk, hkkk, gh,
                              tdecay, dw2, taaaaa, aaa_w2, tmisca, ma_w2,
                              tmisck, mk_w2, kkk_w2, gate_w2,
                              Dec, A, KK, K, G);
    k_kknorm<<<TT, 256>>>(KK);
    k_wkv<<<dim3(HH, 4), 256>>>(R, Dec, K, KK, A, V, Y);
    k_gn<<<TT, 512>>>(Y, R, K, V, G, faaaa, lnw, lnb, YM);
    k_sgemm<<<gg, 256>>>(YM, Wo, out, TT, CC, CC);
}

// round 4
// speedup vs baseline: 1.2045x; 1.2045x over previous
#include <cuda_runtime.h>
#include <cuda_bf16.h>
#include <math.h>
#include <stdint.h>

#define TT 1024
#define CC 2048
#define HH 32
#define TC (TT*CC)
#define EPSGN 0.00064f

// ---------------- scratch ----------------
__device__ __align__(128) float g_scratch[16ull*TC + 2ull*TT*128 + (size_t)TT*64 + 4ull*TT*16];
__device__ __align__(128) __nv_bfloat16 g_bf[2ull*CC*CC + 2ull*TT*CC];

#define O_DXP   ((size_t)0*TC)
#define O_XXX   ((size_t)1*TC)
#define O_XRG   ((size_t)2*TC)
#define O_XWA   ((size_t)3*TC)
#define O_XK    ((size_t)4*TC)
#define O_XV    ((size_t)5*TC)
#define O_R     ((size_t)6*TC)
#define O_KRAW  ((size_t)7*TC)
#define O_V     ((size_t)8*TC)
#define O_DEC   ((size_t)9*TC)
#define O_A     ((size_t)10*TC)
#define O_KK    ((size_t)11*TC)
#define O_K     ((size_t)12*TC)
#define O_G     ((size_t)13*TC)
#define O_Y     ((size_t)14*TC)
#define O_YM    ((size_t)15*TC)
#define O_HMIX  ((size_t)16*TC)
#define O_GH    (O_HMIX + (size_t)TT*128)
#define O_HD    (O_GH   + (size_t)TT*128)
#define O_HAAA  (O_HD   + (size_t)TT*64)
#define O_HMA   (O_HAAA + (size_t)TT*16)
#define O_HMK   (O_HMA  + (size_t)TT*16)
#define O_HKKK  (O_HMK  + (size_t)TT*16)

// ---------------- helpers ----------------
__device__ __forceinline__ uint32_t smem_u32(const void* p) {
    uint32_t a;
    asm("{ .reg .u64 t; cvta.to.shared.u64 t, %1; cvt.u32.u64 %0, t; }" : "=r"(a) : "l"(p));
    return a;
}
__device__ __forceinline__ void ldm4(uint32_t r[4], uint32_t a) {
    asm volatile("ldmatrix.sync.aligned.m8n8.x4.shared.b16 {%0,%1,%2,%3}, [%4];"
                 : "=r"(r[0]), "=r"(r[1]), "=r"(r[2]), "=r"(r[3]) : "r"(a));
}
__device__ __forceinline__ void mma16816(float c[4], const uint32_t a[4], uint32_t b0, uint32_t b1) {
    asm volatile("mma.sync.aligned.m16n8k16.row.col.f32.bf16.bf16.f32 "
                 "{%0,%1,%2,%3},{%4,%5,%6,%7},{%8,%9},{%0,%1,%2,%3};"
                 : "+f"(c[0]), "+f"(c[1]), "+f"(c[2]), "+f"(c[3])
                 : "r"(a[0]), "r"(a[1]), "r"(a[2]), "r"(a[3]), "r"(b0), "r"(b1));
}
#define CPA16(dst, src) asm volatile("cp.async.ca.shared.global [%0], [%1], 16;" :: "r"(dst), "l"(src))
#define CPA_COMMIT() asm volatile("cp.async.commit_group;" ::: "memory")

// ---------------- token shift ----------------
__global__ void k_tokshift(const float* __restrict__ x, const float* __restrict__ maa_x,
                           float* __restrict__ dxp, float* __restrict__ xxx) {
    int idx = blockIdx.x * blockDim.x + threadIdx.x;
    if (idx >= TC) return;
    int t = idx >> 11, c = idx & (CC - 1);
    float xv = x[idx];
    float pv = (t > 0) ? x[idx - CC] : 0.0f;
    float dx = pv - xv;
    dxp[idx] = dx;
    xxx[idx] = fmaf(dx, maa_x[c], xv);
}

// ---------------- narrow GEMM ----------------
template <int NN, bool ACT>
__global__ void k_gemm_small(const float* __restrict__ A, const float* __restrict__ W,
                             float* __restrict__ out) {
    constexpr int G = 128 / NN, RPT = 4, RT = G * RPT, KC = 64;
    __shared__ float As[RT][KC + 1];
    const int n = threadIdx.x % NN, g = threadIdx.x / NN;
    const int r0 = blockIdx.x * RT;
    float acc[RPT];
#pragma unroll
    for (int i = 0; i < RPT; i++) acc[i] = 0.f;
    for (int kc = 0; kc < CC; kc += KC) {
        __syncthreads();
        for (int i = threadIdx.x; i < RT * KC; i += 128) {
            int rr = i / KC, ck = i % KC;
            As[rr][ck] = A[(size_t)(r0 + rr) * CC + kc + ck];
        }
        __syncthreads();
#pragma unroll 4
        for (int k = 0; k < KC; k++) {
            float wv = W[(size_t)(kc + k) * NN + n];
#pragma unroll
            for (int i = 0; i < RPT; i++)
                acc[i] = fmaf(As[g * RPT + i][k], wv, acc[i]);
        }
    }
#pragma unroll
    for (int i = 0; i < RPT; i++) {
        float v = acc[i];
        if (ACT) v = tanhf(v);
        out[(size_t)(r0 + g * RPT + i) * NN + n] = v;
    }
}

// ---------------- mix apply ----------------
__global__ void k_mix_apply(const float* __restrict__ x, const float* __restrict__ dxp,
                            const float* __restrict__ hmix, const float* __restrict__ w2full,
                            const float* __restrict__ tm0, const float* __restrict__ tm1,
                            const float* __restrict__ tm2, const float* __restrict__ tm3,
                            float* __restrict__ o0, float* __restrict__ o1,
                            float* __restrict__ o2, float* __restrict__ o3) {
    const int f = blockIdx.z, t0 = blockIdx.y * 8;
    const int c = blockIdx.x * 128 + threadIdx.x;
    __shared__ float hm[8][32];
    for (int i = threadIdx.x; i < 8 * 32; i += 128) {
        int tt = i >> 5, d = i & 31;
        hm[tt][d] = hmix[(size_t)(t0 + tt) * 128 + f * 32 + d];
    }
    __syncthreads();
    const float* w2 = w2full + (size_t)f * 32 * CC;
    float acc[8];
#pragma unroll
    for (int i = 0; i < 8; i++) acc[i] = 0.f;
#pragma unroll 4
    for (int d = 0; d < 32; d++) {
        float wv = w2[(size_t)d * CC + c];
#pragma unroll
        for (int tt = 0; tt < 8; tt++) acc[tt] = fmaf(hm[tt][d], wv, acc[tt]);
    }
    const float* tm  = (f == 0) ? tm0 : (f == 1) ? tm1 : (f == 2) ? tm2 : tm3;
    float*       out = (f == 0) ? o0  : (f == 1) ? o1  : (f == 2) ? o2  : o3;
    float tmv = tm[c];
#pragma unroll
    for (int tt = 0; tt < 8; tt++) {
        size_t idx = (size_t)(t0 + tt) * CC + c;
        out[idx] = fmaf(dxp[idx], tmv + acc[tt], x[idx]);
    }
}

// ---------------- weight prep: W[K,N]f32 -> WT[N,K] bf16 hi/lo ----------------
__global__ void k_wprep(const float* __restrict__ W, __nv_bfloat16* __restrict__ Thi,
                        __nv_bfloat16* __restrict__ Tlo) {
    __shared__ float tl[32][33];
    const int n0 = blockIdx.x * 32, k0 = blockIdx.y * 32;
    const int tx = threadIdx.x, ty = threadIdx.y;
#pragma unroll
    for (int j = 0; j < 32; j += 8)
        tl[ty + j][tx] = W[(size_t)(k0 + ty + j) * CC + n0 + tx];
    __syncthreads();
#pragma unroll
    for (int j = 0; j < 32; j += 8) {
        float v = tl[tx][ty + j];
        __nv_bfloat16 h = __float2bfloat16(v);
        size_t o = (size_t)(n0 + ty + j) * CC + k0 + tx;
        Thi[o] = h;
        Tlo[o] = __float2bfloat16(v - __bfloat162float(h));
    }
}

// ---------------- activation prep ----------------
__global__ void k_aprep(const float* __restrict__ X, __nv_bfloat16* __restrict__ hi,
                        __nv_bfloat16* __restrict__ lo) {
    int i = blockIdx.x * 256 + threadIdx.x;
    float v = X[i];
    __nv_bfloat16 h = __float2bfloat16(v);
    hi[i] = h;
    lo[i] = __float2bfloat16(v - __bfloat162float(h));
}

// ---------------- mma.sync split-bf16 GEMM: C[M,CC] = A[M,K] @ B[N,K]^T ----------------
// CTA 128x128, BK=32, 8 warps (64x32 each), cp.async double buffer.
#define RS 40                      // smem row stride in halves (80B: conflict-free ldmatrix)
#define TILE_H (128 * RS)          // halves per operand tile
#define STAGE_H (4 * TILE_H)       // halves per stage (Ahi,Alo,Bhi,Blo)
#define GM_SMEM (2 * STAGE_H * 2)  // bytes
__global__ __launch_bounds__(256) void k_bigmm(
    const __nv_bfloat16* __restrict__ Ahi, const __nv_bfloat16* __restrict__ Alo,
    const __nv_bfloat16* __restrict__ Bhi, const __nv_bfloat16* __restrict__ Blo,
    float* __restrict__ C) {
    extern __shared__ __align__(16) __nv_bfloat16 sm[];
    const int tid = threadIdx.x, wid = tid >> 5, lane = tid & 31;
    const int bn = blockIdx.x * 128, bm = blockIdx.y * 128;
    const int wm = wid & 1, wn = wid >> 1;
    const uint32_t sb = smem_u32(sm);

    const __nv_bfloat16* gsrc[4] = {
        Ahi + (size_t)bm * CC, Alo + (size_t)bm * CC,
        Bhi + (size_t)bn * CC, Blo + (size_t)bn * CC };

    float acc[4][4][4];
#pragma unroll
    for (int a = 0; a < 4; a++)
#pragma unroll
        for (int b = 0; b < 4; b++)
#pragma unroll
            for (int c = 0; c < 4; c++) acc[a][b][c] = 0.f;

    const int r = tid >> 2, cb = tid & 3;          // loader coords: 2 chunk-sets of 128B
    // issue one stage of cp.async
    auto load_stage = [&](int kc, int stg) {
#pragma unroll
        for (int tl = 0; tl < 4; tl++) {
            const __nv_bfloat16* s = gsrc[tl] + kc;
            uint32_t d = sb + (uint32_t)(stg * STAGE_H + tl * TILE_H) * 2;
#pragma unroll
            for (int j = 0; j < 2; j++) {
                int rr = r + j * 64;
                CPA16(d + (uint32_t)(rr * RS + cb * 8) * 2, s + (size_t)rr * CC + cb * 8);
            }
        }
        CPA_COMMIT();
    };

    const int KT = CC / 32;
    load_stage(0, 0);

    for (int kt = 0; kt < KT; kt++) {
        const int stg = kt & 1;
        if (kt + 1 < KT) {
            load_stage((kt + 1) * 32, stg ^ 1);
            asm volatile("cp.async.wait_group 1;" ::: "memory");
        } else {
            asm volatile("cp.async.wait_group 0;" ::: "memory");
        }
        __syncthreads();

        const uint32_t sA_hi = sb + (uint32_t)(stg * STAGE_H + 0 * TILE_H) * 2;
        const uint32_t sA_lo = sb + (uint32_t)(stg * STAGE_H + 1 * TILE_H) * 2;
        const uint32_t sB_hi = sb + (uint32_t)(stg * STAGE_H + 2 * TILE_H) * 2;
        const uint32_t sB_lo = sb + (uint32_t)(stg * STAGE_H + 3 * TILE_H) * 2;

#pragma unroll
        for (int ks = 0; ks < 2; ks++) {
            uint32_t ah[4][4], al[4][4], bh[2][4], bl[2][4];
#pragma unroll
            for (int mf = 0; mf < 4; mf++) {
                int row = wm * 64 + mf * 16 + (lane & 15);
                int col = ks * 16 + ((lane >> 4) << 3);
                uint32_t off = (uint32_t)(row * RS + col) * 2;
                ldm4(ah[mf], sA_hi + off);
                ldm4(al[mf], sA_lo + off);
            }
#pragma unroll
            for (int p = 0; p < 2; p++) {
                int n = wn * 32 + p * 16 + ((lane >> 4) << 3) + (lane & 7);
                int k = ks * 16 + (((lane >> 3) & 1) << 3);
                uint32_t off = (uint32_t)(n * RS + k) * 2;
                ldm4(bh[p], sB_hi + off);
                ldm4(bl[p], sB_lo + off);
            }
#pragma unroll
            for (int mf = 0; mf < 4; mf++)
#pragma unroll
                for (int nf = 0; nf < 4; nf++) {
                    const int p = nf >> 1, q = (nf & 1) * 2;
                    mma16816(acc[mf][nf], ah[mf], bh[p][q], bh[p][q + 1]); // hi*hi
                    mma16816(acc[mf][nf], ah[mf], bl[p][q], bl[p][q + 1]); // hi*lo
                    mma16816(acc[mf][nf], al[mf], bh[p][q], bh[p][q + 1]); // lo*hi
                }
        }
        __syncthreads();
    }

#pragma unroll
    for (int mf = 0; mf < 4; mf++)
#pragma unroll
        for (int nf = 0; nf < 4; nf++) {
            int row = bm + wm * 64 + mf * 16 + (lane >> 2);
            int col = bn + wn * 32 + nf * 8 + (lane & 3) * 2;
            *(float2*)&C[(size_t)row * CC + col] =
                make_float2(acc[mf][nf][0], acc[mf][nf][1]);
            *(float2*)&C[(size_t)(row + 8) * CC + col] =
                make_float2(acc[mf][nf][2], acc[mf][nf][3]);
        }
}

// ---------------- stage 2 (fast math) ----------------
__global__ __launch_bounds__(256) void k_stage2(
    const float* __restrict__ kraw_in,
    const float* __restrict__ hd,   const float* __restrict__ haaa,
    const float* __restrict__ hma,  const float* __restrict__ hmk,
    const float* __restrict__ hkkk, const float* __restrict__ gh,
    const float* __restrict__ td,   const float* __restrict__ dw2,
    const float* __restrict__ taa,  const float* __restrict__ aw2,
    const float* __restrict__ tmisca, const float* __restrict__ maw2,
    const float* __restrict__ tmisck, const float* __restrict__ mkw2,
    const float* __restrict__ kkkw2,  const float* __restrict__ gw2,
    float* __restrict__ decout, float* __restrict__ aout,
    float* __restrict__ kkout,  float* __restrict__ kout, float* __restrict__ gout) {
    const int t0 = blockIdx.x * 8, tid = threadIdx.x;
    __shared__ float shd[8][64];
    __shared__ float sh16[4][8][16];
    __shared__ float shg[8][128];
    for (int i = tid; i < 8 * 64; i += 256)
        shd[i >> 6][i & 63] = hd[(size_t)(t0 + (i >> 6)) * 64 + (i & 63)];
    for (int i = tid; i < 8 * 16; i += 256) {
        int rr = i >> 4, j = i & 15;
        sh16[0][rr][j] = haaa[(size_t)(t0 + rr) * 16 + j];
        sh16[1][rr][j] = hma [(size_t)(t0 + rr) * 16 + j];
        sh16[2][rr][j] = hmk [(size_t)(t0 + rr) * 16 + j];
        sh16[3][rr][j] = hkkk[(size_t)(t0 + rr) * 16 + j];
    }
    for (int i = tid; i < 8 * 128; i += 256)
        shg[i >> 7][i & 127] = gh[(size_t)(t0 + (i >> 7)) * 128 + (i & 127)];
    __syncthreads();

    for (int c = tid; c < CC; c += 256) {
        float ud[8], ua[8], uma[8], umk[8], ukk[8], ug[8];
#pragma unroll
        for (int rr = 0; rr < 8; rr++) { ud[rr]=0.f; ua[rr]=0.f; uma[rr]=0.f; umk[rr]=0.f; ukk[rr]=0.f; ug[rr]=0.f; }
#pragma unroll 4
        for (int j = 0; j < 64; j++) {
            float w = dw2[(size_t)j * CC + c];
#pragma unroll
            for (int rr = 0; rr < 8; rr++) ud[rr] = fmaf(shd[rr][j], w, ud[rr]);
        }
#pragma unroll 2
        for (int j = 0; j < 16; j++) {
            float w1 = aw2[(size_t)j * CC + c],  w2v = maw2[(size_t)j * CC + c];
            float w3 = mkw2[(size_t)j * CC + c], w4  = kkkw2[(size_t)j * CC + c];
#pragma unroll
            for (int rr = 0; rr < 8; rr++) {
                ua[rr]  = fmaf(sh16[0][rr][j], w1,  ua[rr]);
                uma[rr] = fmaf(sh16[1][rr][j], w2v, uma[rr]);
                umk[rr] = fmaf(sh16[2][rr][j], w3,  umk[rr]);
                ukk[rr] = fmaf(sh16[3][rr][j], w4,  ukk[rr]);
            }
        }
#pragma unroll 4
        for (int j = 0; j < 128; j++) {
            float w = gw2[(size_t)j * CC + c];
#pragma unroll
            for (int rr = 0; rr < 8; rr++) ug[rr] = fmaf(shg[rr][j], w, ug[rr]);
        }
        float tdv = td[c], taav = taa[c], tmav = tmisca[c], tmkv = tmisck[c];
#pragma unroll
        for (int rr = 0; rr < 8; rr++) {
            size_t idx = (size_t)(t0 + rr) * CC + c;
            float z  = tdv + ud[rr];
            float wv = -(fmaxf(-z, 0.f) + __logf(1.f + __expf(-fabsf(z)))) - 0.5f;
            decout[idx] = __expf(wv);
            float av  = __fdividef(1.f, 1.f + __expf(-(taav + ua[rr])));
            aout[idx] = av;
            float mav = __fdividef(1.f, 1.f + __expf(-(tmav + uma[rr])));
            float mkv = __fdividef(1.f, 1.f + __expf(-(tmkv + umk[rr])));
            float kr  = kraw_in[idx];
            kkout[idx] = kr + ukk[rr];
            float km = kr * (mav + av * (1.f - mav));
            km *= __expf(fminf(wv * mkv, 0.f));
            kout[idx] = km;
            gout[idx] = ug[rr];
        }
    }
}

// ---------------- kk norm ----------------
__global__ void k_kknorm(float* __restrict__ kk) {
    const int t = blockIdx.x, tid = threadIdx.x;
    const size_t base = (size_t)t * CC + tid * 8;
    float4 a = *(float4*)&kk[base];
    float4 b = *(float4*)&kk[base + 4];
    float ss = a.x*a.x + a.y*a.y + a.z*a.z + a.w*a.w
             + b.x*b.x + b.y*b.y + b.z*b.z + b.w*b.w;
    ss += __shfl_xor_sync(0xffffffffu, ss, 1);
    ss += __shfl_xor_sync(0xffffffffu, ss, 2);
    ss += __shfl_xor_sync(0xffffffffu, ss, 4);
    float inv = __fdividef(1.f, fmaxf(sqrtf(ss), 1e-12f));
    a.x *= inv; a.y *= inv; a.z *= inv; a.w *= inv;
    b.x *= inv; b.y *= inv; b.z *= inv; b.w *= inv;
    *(float4*)&kk[base]     = a;
    *(float4*)&kk[base + 4] = b;
}

// ---------------- WKV7 with register prefetch ----------------
__global__ __launch_bounds__(256) void k_wkv(
    const float* __restrict__ R, const float* __restrict__ Dec,
    const float* __restrict__ K, const float* __restrict__ Kk,
    const float* __restrict__ Asig, const float* __restrict__ V,
    float* __restrict__ Y) {
    const int h = blockIdx.x, rb = blockIdx.y, tid = threadIdx.x;
    const int il = tid >> 4, cg = tid & 15;
    const int i = rb * 16 + il;
    const int colbase = h * 64 + cg * 4;
    const int rowidx  = h * 64 + i;

    float4 s = make_float4(0.f, 0.f, 0.f, 0.f);
    float4 kkv = *(const float4*)&Kk[colbase];
    float4 dv  = *(const float4*)&Dec[colbase];
    float4 kv  = *(const float4*)&K[colbase];
    float4 rv  = *(const float4*)&R[colbase];
    float4 av  = *(const float4*)&Asig[colbase];
    float  vi  = V[rowidx];

    for (int t = 0; t < TT; t++) {
        const size_t nb = (size_t)((t + 1 < TT) ? (t + 1) : t) * CC;
        float4 kk2 = *(const float4*)&Kk[nb + colbase];
        float4 dv2 = *(const float4*)&Dec[nb + colbase];
        float4 kv2 = *(const float4*)&K[nb + colbase];
        float4 rv2 = *(const float4*)&R[nb + colbase];
        float4 av2 = *(const float4*)&Asig[nb + colbase];
        float  vi2 = V[nb + rowidx];

        float sa = s.x*kkv.x + s.y*kkv.y + s.z*kkv.z + s.w*kkv.w;
        sa += __shfl_xor_sync(0xffffffffu, sa, 1);
        sa += __shfl_xor_sync(0xffffffffu, sa, 2);
        sa += __shfl_xor_sync(0xffffffffu, sa, 4);
        sa += __shfl_xor_sync(0xffffffffu, sa, 8);
        sa = -sa;

        s.x = fmaf(vi, kv.x, fmaf(sa, kkv.x*av.x, s.x*dv.x));
        s.y = fmaf(vi, kv.y, fmaf(sa, kkv.y*av.y, s.y*dv.y));
        s.z = fmaf(vi, kv.z, fmaf(sa, kkv.z*av.z, s.z*dv.z));
        s.w = fmaf(vi, kv.w, fmaf(sa, kkv.w*av.w, s.w*dv.w));

        float o = s.x*rv.x + s.y*rv.y + s.z*rv.z + s.w*rv.w;
        o += __shfl_xor_sync(0xffffffffu, o, 1);
        o += __shfl_xor_sync(0xffffffffu, o, 2);
        o += __shfl_xor_sync(0xffffffffu, o, 4);
        o += __shfl_xor_sync(0xffffffffu, o, 8);
        if (cg == 0) Y[(size_t)t * CC + rowidx] = o;

        kkv = kk2; dv = dv2; kv = kv2; rv = rv2; av = av2; vi = vi2;
    }
}

// ---------------- groupnorm + bonus + gate ----------------
__global__ __launch_bounds__(512) void k_gn(
    const float* __restrict__ Yin, const float* __restrict__ R,
    const float* __restrict__ K,   const float* __restrict__ V,
    const float* __restrict__ G,   const float* __restrict__ faaaa,
    const float* __restrict__ lnw, const float* __restrict__ lnb,
    float* __restrict__ Yout) {
    const int t = blockIdx.x, tid = threadIdx.x;
    const int c = tid * 4;
    const size_t idx = (size_t)t * CC + c;
    float4 y  = *(const float4*)&Yin[idx];
    float4 r4 = *(const float4*)&R[idx];
    float4 k4 = *(const float4*)&K[idx];
    float4 v4 = *(const float4*)&V[idx];
    float4 g4 = *(const float4*)&G[idx];
    float4 f4 = *(const float4*)&faaaa[c];
    float4 w4 = *(const float4*)&lnw[c];
    float4 b4 = *(const float4*)&lnb[c];

    float s1 = y.x + y.y + y.z + y.w;
    float s2 = y.x*y.x + y.y*y.y + y.z*y.z + y.w*y.w;
    float s3 = r4.x*k4.x*f4.x + r4.y*k4.y*f4.y + r4.z*k4.z*f4.z + r4.w*k4.w*f4.w;
#pragma unroll
    for (int m = 1; m <= 8; m <<= 1) {
        s1 += __shfl_xor_sync(0xffffffffu, s1, m);
        s2 += __shfl_xor_sync(0xffffffffu, s2, m);
        s3 += __shfl_xor_sync(0xffffffffu, s3, m);
    }
    float mu  = s1 * (1.f / 64.f);
    float var = s2 * (1.f / 64.f) - mu * mu;
    float rs  = rsqrtf(var + EPSGN);
    float4 o;
    o.x = (fmaf((y.x - mu) * rs, w4.x, b4.x) + s3 * v4.x) * g4.x;
    o.y = (fmaf((y.y - mu) * rs, w4.y, b4.y) + s3 * v4.y) * g4.y;
    o.z = (fmaf((y.z - mu) * rs, w4.z, b4.z) + s3 * v4.z) * g4.z;
    o.w = (fmaf((y.w - mu) * rs, w4.w, b4.w) + s3 * v4.w) * g4.w;
    *(float4*)&Yout[idx] = o;
}

// ---------------------------------------------------------------------------
extern "C" void kernel_launch(void* const* d_in, const int* in_sizes, int n_in,
                              void* d_out, int out_size) {
    const float* x      = (const float*)d_in[0];
    const float* Wq     = (const float*)d_in[1];
    const float* Wk     = (const float*)d_in[2];
    const float* Wv     = (const float*)d_in[3];
    const float* Wo     = (const float*)d_in[4];
    const float* tmx    = (const float*)d_in[5];
    const float* tmrg   = (const float*)d_in[6];
    const float* tmwa   = (const float*)d_in[7];
    const float* tmk    = (const float*)d_in[8];
    const float* tmv    = (const float*)d_in[9];
    const float* maa_w1 = (const float*)d_in[10];
    const float* maa_w2 = (const float*)d_in[11];
    const float* tdecay = (const float*)d_in[12];
    const float* dw1    = (const float*)d_in[13];
    const float* dw2    = (const float*)d_in[14];
    const float* taaaaa = (const float*)d_in[15];
    const float* aaa_w1 = (const float*)d_in[16];
    const float* aaa_w2 = (const float*)d_in[17];
    const float* kkk_w1 = (const float*)d_in[18];
    const float* kkk_w2 = (const float*)d_in[19];
    const float* gate_w1 = (const float*)d_in[20];
    const float* gate_w2 = (const float*)d_in[21];
    const float* tmisca = (const float*)d_in[22];
    const float* ma_w1  = (const float*)d_in[23];
    const float* ma_w2  = (const float*)d_in[24];
    const float* tmisck = (const float*)d_in[25];
    const float* mk_w1  = (const float*)d_in[26];
    const float* mk_w2  = (const float*)d_in[27];
    const float* faaaa  = (const float*)d_in[28];
    const float* lnw    = (const float*)d_in[29];
    const float* lnb    = (const float*)d_in[30];
    float* out = (float*)d_out;

    float* S = nullptr;
    cudaGetSymbolAddress((void**)&S, g_scratch);
    __nv_bfloat16* BF = nullptr;
    cudaGetSymbolAddress((void**)&BF, g_bf);

    float* dxp  = S + O_DXP;  float* xxx  = S + O_XXX;
    float* xrg  = S + O_XRG;  float* xwa  = S + O_XWA;
    float* xk   = S + O_XK;   float* xv   = S + O_XV;
    float* R    = S + O_R;    float* Kraw = S + O_KRAW;
    float* V    = S + O_V;    float* Dec  = S + O_DEC;
    float* A    = S + O_A;    float* KK   = S + O_KK;
    float* K    = S + O_K;    float* G    = S + O_G;
    float* Y    = S + O_Y;    float* YM   = S + O_YM;
    float* hmix = S + O_HMIX; float* gh   = S + O_GH;
    float* hd   = S + O_HD;   float* haaa = S + O_HAAA;
    float* hma  = S + O_HMA;  float* hmk  = S + O_HMK;
    float* hkkk = S + O_HKKK;

    __nv_bfloat16* WThi = BF;
    __nv_bfloat16* WTlo = BF + (size_t)CC * CC;
    __nv_bfloat16* Ahi  = BF + 2ull * CC * CC;
    __nv_bfloat16* Alo  = Ahi + (size_t)TT * CC;

    cudaFuncSetAttribute(k_bigmm, cudaFuncAttributeMaxDynamicSharedMemorySize, GM_SMEM);

    dim3 wg(64, 64);
    dim3 wb(32, 8);
    dim3 mg(CC / 128, TT / 128);

    k_tokshift<<<TC / 256, 256>>>(x, tmx, dxp, xxx);
    k_gemm_small<128, true><<<TT / 4, 128>>>(xxx, maa_w1, hmix);
    k_mix_apply<<<dim3(CC / 128, TT / 8, 4), 128>>>(x, dxp, hmix, maa_w2,
                                                    tmrg, tmwa, tmk, tmv,
                                                    xrg, xwa, xk, xv);

    k_wprep<<<wg, wb>>>(Wq, WThi, WTlo);
    k_aprep<<<TC / 256, 256>>>(xrg, Ahi, Alo);
    k_bigmm<<<mg, 256, GM_SMEM>>>(Ahi, Alo, WThi, WTlo, R);   // ncu-captured launch (#6)

    k_wprep<<<wg, wb>>>(Wk, WThi, WTlo);
    k_aprep<<<TC / 256, 256>>>(xk, Ahi, Alo);
    k_bigmm<<<mg, 256, GM_SMEM>>>(Ahi, Alo, WThi, WTlo, Kraw);

    k_wprep<<<wg, wb>>>(Wv, WThi, WTlo);
    k_aprep<<<TC / 256, 256>>>(xv, Ahi, Alo);
    k_bigmm<<<mg, 256, GM_SMEM>>>(Ahi, Alo, WThi, WTlo, V);

    k_gemm_small<64,  true ><<<TT / 8,  128>>>(xwa, dw1,    hd);
    k_gemm_small<16,  false><<<TT / 32, 128>>>(xwa, aaa_w1, haaa);
    k_gemm_small<16,  false><<<TT / 32, 128>>>(xwa, ma_w1,  hma);
    k_gemm_small<16,  false><<<TT / 32, 128>>>(xk,  mk_w1,  hmk);
    k_gemm_small<16,  true ><<<TT / 32, 128>>>(xk,  kkk_w1, hkkk);
    k_gemm_small<128, true ><<<TT / 4,  128>>>(xrg, gate_w1, gh);

    k_stage2<<<TT / 8, 256>>>(Kraw, hd, haaa, hma, hmk, hkkk, gh,
                              tdecay, dw2, taaaaa, aaa_w2, tmisca, ma_w2,
                              tmisck, mk_w2, kkk_w2, gate_w2,
                              Dec, A, KK, K, G);
    k_kknorm<<<TT, 256>>>(KK);
    k_wkv<<<dim3(HH, 4), 256>>>(R, Dec, K, KK, A, V, Y);
    k_gn<<<TT, 512>>>(Y, R, K, V, G, faaaa, lnw, lnb, YM);

    k_wprep<<<wg, wb>>>(Wo, WThi, WTlo);
    k_aprep<<<TC / 256, 256>>>(YM, Ahi, Alo);
    k_bigmm<<<mg, 256, GM_SMEM>>>(Ahi, Alo, WThi, WTlo, out);
}

// round 5
// speedup vs baseline: 2.2599x; 1.8761x over previous
#include <cuda_runtime.h>
#include <cuda_bf16.h>
#include <math.h>
#include <stdint.h>

#define TT 1024
#define CC 2048
#define HH 32
#define TC (TT*CC)
#define EPSGN 0.00064f

// ---------------- scratch ----------------
__device__ __align__(128) float g_scratch[16ull*TC + 2ull*TT*128 + (size_t)TT*64 + 4ull*TT*16];
__device__ __align__(128) __nv_bfloat16 g_bf[2ull*CC*CC + 2ull*TT*CC];

#define O_DXP   ((size_t)0*TC)
#define O_XXX   ((size_t)1*TC)
#define O_XRG   ((size_t)2*TC)
#define O_XWA   ((size_t)3*TC)
#define O_XK    ((size_t)4*TC)
#define O_XV    ((size_t)5*TC)
#define O_R     ((size_t)6*TC)
#define O_KRAW  ((size_t)7*TC)
#define O_V     ((size_t)8*TC)
#define O_DEC   ((size_t)9*TC)
#define O_A     ((size_t)10*TC)
#define O_KK    ((size_t)11*TC)
#define O_K     ((size_t)12*TC)
#define O_G     ((size_t)13*TC)
#define O_Y     ((size_t)14*TC)
#define O_YM    ((size_t)15*TC)
#define O_HMIX  ((size_t)16*TC)
#define O_GH    (O_HMIX + (size_t)TT*128)
#define O_HD    (O_GH   + (size_t)TT*128)
#define O_HAAA  (O_HD   + (size_t)TT*64)
#define O_HMA   (O_HAAA + (size_t)TT*16)
#define O_HMK   (O_HMA  + (size_t)TT*16)
#define O_HKKK  (O_HMK  + (size_t)TT*16)

// ---------------- helpers ----------------
__device__ __forceinline__ uint32_t smem_u32(const void* p) {
    uint32_t a;
    asm("{ .reg .u64 t; cvta.to.shared.u64 t, %1; cvt.u32.u64 %0, t; }" : "=r"(a) : "l"(p));
    return a;
}
__device__ __forceinline__ void ldm4(uint32_t r[4], uint32_t a) {
    asm volatile("ldmatrix.sync.aligned.m8n8.x4.shared.b16 {%0,%1,%2,%3}, [%4];"
                 : "=r"(r[0]), "=r"(r[1]), "=r"(r[2]), "=r"(r[3]) : "r"(a));
}
__device__ __forceinline__ void mma16816(float c[4], const uint32_t a[4], uint32_t b0, uint32_t b1) {
    asm volatile("mma.sync.aligned.m16n8k16.row.col.f32.bf16.bf16.f32 "
                 "{%0,%1,%2,%3},{%4,%5,%6,%7},{%8,%9},{%0,%1,%2,%3};"
                 : "+f"(c[0]), "+f"(c[1]), "+f"(c[2]), "+f"(c[3])
                 : "r"(a[0]), "r"(a[1]), "r"(a[2]), "r"(a[3]), "r"(b0), "r"(b1));
}
#define CPA16(dst, src) asm volatile("cp.async.ca.shared.global [%0], [%1], 16;" :: "r"(dst), "l"(src))
#define CPA4(dst, src)  asm volatile("cp.async.ca.shared.global [%0], [%1], 4;"  :: "r"(dst), "l"(src))
#define CPA_COMMIT() asm volatile("cp.async.commit_group;" ::: "memory")

// ---------------- token shift ----------------
__global__ void k_tokshift(const float* __restrict__ x, const float* __restrict__ maa_x,
                           float* __restrict__ dxp, float* __restrict__ xxx) {
    int idx = blockIdx.x * blockDim.x + threadIdx.x;
    if (idx >= TC) return;
    int t = idx >> 11, c = idx & (CC - 1);
    float xv = x[idx];
    float pv = (t > 0) ? x[idx - CC] : 0.0f;
    float dx = pv - xv;
    dxp[idx] = dx;
    xxx[idx] = fmaf(dx, maa_x[c], xv);
}

// ---------------- k_proj: out = act(A[T,CC] @ W[CC,NN]), smem-staged ----------------
// block 256, 8 rows per block, K-chunks of 64, cp.async double buffer.
// cols [0,SPLIT) from W0 -> out0 (tanh if ACT0), [SPLIT,NN) from W1 -> out1 (tanh if ACT1).
template <int NN, int SPLIT, int ACT0, int ACT1>
__global__ __launch_bounds__(256) void k_proj(const float* __restrict__ A,
                                              const float* __restrict__ W0,
                                              const float* __restrict__ W1,
                                              float* __restrict__ out0,
                                              float* __restrict__ out1) {
    constexpr int G = 256 / NN;      // row groups
    constexpr int R = 8 / G;         // rows per thread
    constexpr int WCH = 64 * NN;     // floats per W chunk
    extern __shared__ __align__(16) float psm[];
    float* Ws = psm;                 // [2][WCH]
    float* As = psm + 2 * WCH;       // [2][64*8], layout [k][row]
    const uint32_t ws_b = smem_u32(Ws);
    const uint32_t as_b = smem_u32(As);

    const int tid = threadIdx.x;
    const int n = tid % NN, g = tid / NN;
    const int r0 = blockIdx.x * 8;

    auto load_stage = [&](int kc, int stg) {
        // W chunk: 16B per copy
#pragma unroll
        for (int j = 0; j < WCH / 1024; j++) {
            int i = (tid + j * 256) * 4;
            int row = i / NN, col = i % NN;
            const float* src = (col < SPLIT)
                ? (W0 + (size_t)(kc + row) * SPLIT + col)
                : (W1 + (size_t)(kc + row) * (NN - SPLIT) + (col - SPLIT));
            CPA16(ws_b + (uint32_t)(stg * WCH + i) * 4, src);
        }
        // A chunk transposed: 4B per copy
#pragma unroll
        for (int j = 0; j < 2; j++) {
            int i = tid + j * 256;
            int row = i >> 6, k = i & 63;
            CPA4(as_b + (uint32_t)(stg * 512 + k * 8 + row) * 4,
                 A + (size_t)(r0 + row) * CC + kc + k);
        }
        CPA_COMMIT();
    };

    float acc[R];
#pragma unroll
    for (int i = 0; i < R; i++) acc[i] = 0.f;

    load_stage(0, 0);
    for (int ch = 0; ch < 32; ch++) {
        const int b = ch & 1;
        if (ch + 1 < 32) {
            load_stage((ch + 1) * 64, b ^ 1);
            asm volatile("cp.async.wait_group 1;" ::: "memory");
        } else {
            asm volatile("cp.async.wait_group 0;" ::: "memory");
        }
        __syncthreads();
        const float* ws = Ws + b * WCH;
        const float* as = As + b * 512;
#pragma unroll 8
        for (int k = 0; k < 64; k++) {
            float wv = ws[k * NN + n];
            if (R == 4) {
                float4 a4 = *(const float4*)&as[k * 8 + g * 4];
                acc[0] = fmaf(a4.x, wv, acc[0]);
                acc[1] = fmaf(a4.y, wv, acc[1]);
                acc[2] = fmaf(a4.z, wv, acc[2]);
                acc[3] = fmaf(a4.w, wv, acc[3]);
            } else if (R == 2) {
                float2 a2 = *(const float2*)&as[k * 8 + g * 2];
                acc[0] = fmaf(a2.x, wv, acc[0]);
                acc[1] = fmaf(a2.y, wv, acc[1]);
            } else {
                acc[0] = fmaf(as[k * 8 + g], wv, acc[0]);
            }
        }
        __syncthreads();
    }

#pragma unroll
    for (int i = 0; i < R; i++) {
        int row = r0 + g * R + i;
        float v = acc[i];
        if (n < SPLIT) {
            if (ACT0) v = tanhf(v);
            out0[(size_t)row * SPLIT + n] = v;
        } else {
            if (ACT1) v = tanhf(v);
            out1[(size_t)row * (NN - SPLIT) + (n - SPLIT)] = v;
        }
    }
}

// ---------------- mix apply ----------------
__global__ void k_mix_apply(const float* __restrict__ x, const float* __restrict__ dxp,
                            const float* __restrict__ hmix, const float* __restrict__ w2full,
                            const float* __restrict__ tm0, const float* __restrict__ tm1,
                            const float* __restrict__ tm2, const float* __restrict__ tm3,
                            float* __restrict__ o0, float* __restrict__ o1,
                            float* __restrict__ o2, float* __restrict__ o3) {
    const int f = blockIdx.z, t0 = blockIdx.y * 8;
    const int c = blockIdx.x * 128 + threadIdx.x;
    __shared__ float hm[8][32];
    for (int i = threadIdx.x; i < 8 * 32; i += 128) {
        int tt = i >> 5, d = i & 31;
        hm[tt][d] = hmix[(size_t)(t0 + tt) * 128 + f * 32 + d];
    }
    __syncthreads();
    const float* w2 = w2full + (size_t)f * 32 * CC;
    float acc[8];
#pragma unroll
    for (int i = 0; i < 8; i++) acc[i] = 0.f;
#pragma unroll 8
    for (int d = 0; d < 32; d++) {
        float wv = w2[(size_t)d * CC + c];
#pragma unroll
        for (int tt = 0; tt < 8; tt++) acc[tt] = fmaf(hm[tt][d], wv, acc[tt]);
    }
    const float* tm  = (f == 0) ? tm0 : (f == 1) ? tm1 : (f == 2) ? tm2 : tm3;
    float*       out = (f == 0) ? o0  : (f == 1) ? o1  : (f == 2) ? o2  : o3;
    float tmv = tm[c];
#pragma unroll
    for (int tt = 0; tt < 8; tt++) {
        size_t idx = (size_t)(t0 + tt) * CC + c;
        out[idx] = fmaf(dxp[idx], tmv + acc[tt], x[idx]);
    }
}

// ---------------- weight prep: W[K,N]f32 -> WT[N,K] bf16 hi/lo ----------------
__global__ void k_wprep(const float* __restrict__ W, __nv_bfloat16* __restrict__ Thi,
                        __nv_bfloat16* __restrict__ Tlo) {
    __shared__ float tl[32][33];
    const int n0 = blockIdx.x * 32, k0 = blockIdx.y * 32;
    const int tx = threadIdx.x, ty = threadIdx.y;
#pragma unroll
    for (int j = 0; j < 32; j += 8)
        tl[ty + j][tx] = W[(size_t)(k0 + ty + j) * CC + n0 + tx];
    __syncthreads();
#pragma unroll
    for (int j = 0; j < 32; j += 8) {
        float v = tl[tx][ty + j];
        __nv_bfloat16 h = __float2bfloat16(v);
        size_t o = (size_t)(n0 + ty + j) * CC + k0 + tx;
        Thi[o] = h;
        Tlo[o] = __float2bfloat16(v - __bfloat162float(h));
    }
}

// ---------------- activation prep ----------------
__global__ void k_aprep(const float* __restrict__ X, __nv_bfloat16* __restrict__ hi,
                        __nv_bfloat16* __restrict__ lo) {
    int i = blockIdx.x * 256 + threadIdx.x;
    float v = X[i];
    __nv_bfloat16 h = __float2bfloat16(v);
    hi[i] = h;
    lo[i] = __float2bfloat16(v - __bfloat162float(h));
}

// ---------------- mma.sync split-bf16 GEMM ----------------
#define RS 40
#define TILE_H (128 * RS)
#define STAGE_H (4 * TILE_H)
#define GM_SMEM (2 * STAGE_H * 2)
__global__ __launch_bounds__(256) void k_bigmm(
    const __nv_bfloat16* __restrict__ Ahi, const __nv_bfloat16* __restrict__ Alo,
    const __nv_bfloat16* __restrict__ Bhi, const __nv_bfloat16* __restrict__ Blo,
    float* __restrict__ C) {
    extern __shared__ __align__(16) __nv_bfloat16 sm[];
    const int tid = threadIdx.x, wid = tid >> 5, lane = tid & 31;
    const int bn = blockIdx.x * 128, bm = blockIdx.y * 128;
    const int wm = wid & 1, wn = wid >> 1;
    const uint32_t sb = smem_u32(sm);

    const __nv_bfloat16* gsrc[4] = {
        Ahi + (size_t)bm * CC, Alo + (size_t)bm * CC,
        Bhi + (size_t)bn * CC, Blo + (size_t)bn * CC };

    float acc[4][4][4];
#pragma unroll
    for (int a = 0; a < 4; a++)
#pragma unroll
        for (int b = 0; b < 4; b++)
#pragma unroll
            for (int c = 0; c < 4; c++) acc[a][b][c] = 0.f;

    const int r = tid >> 2, cb = tid & 3;
    auto load_stage = [&](int kc, int stg) {
#pragma unroll
        for (int tl = 0; tl < 4; tl++) {
            const __nv_bfloat16* s = gsrc[tl] + kc;
            uint32_t d = sb + (uint32_t)(stg * STAGE_H + tl * TILE_H) * 2;
#pragma unroll
            for (int j = 0; j < 2; j++) {
                int rr = r + j * 64;
                CPA16(d + (uint32_t)(rr * RS + cb * 8) * 2, s + (size_t)rr * CC + cb * 8);
            }
        }
        CPA_COMMIT();
    };

    const int KT = CC / 32;
    load_stage(0, 0);

    for (int kt = 0; kt < KT; kt++) {
        const int stg = kt & 1;
        if (kt + 1 < KT) {
            load_stage((kt + 1) * 32, stg ^ 1);
            asm volatile("cp.async.wait_group 1;" ::: "memory");
        } else {
            asm volatile("cp.async.wait_group 0;" ::: "memory");
        }
        __syncthreads();

        const uint32_t sA_hi = sb + (uint32_t)(stg * STAGE_H + 0 * TILE_H) * 2;
        const uint32_t sA_lo = sb + (uint32_t)(stg * STAGE_H + 1 * TILE_H) * 2;
        const uint32_t sB_hi = sb + (uint32_t)(stg * STAGE_H + 2 * TILE_H) * 2;
        const uint32_t sB_lo = sb + (uint32_t)(stg * STAGE_H + 3 * TILE_H) * 2;

#pragma unroll
        for (int ks = 0; ks < 2; ks++) {
            uint32_t ah[4][4], al[4][4], bh[2][4], bl[2][4];
#pragma unroll
            for (int mf = 0; mf < 4; mf++) {
                int row = wm * 64 + mf * 16 + (lane & 15);
                int col = ks * 16 + ((lane >> 4) << 3);
                uint32_t off = (uint32_t)(row * RS + col) * 2;
                ldm4(ah[mf], sA_hi + off);
                ldm4(al[mf], sA_lo + off);
            }
#pragma unroll
            for (int p = 0; p < 2; p++) {
                int n = wn * 32 + p * 16 + ((lane >> 4) << 3) + (lane & 7);
                int k = ks * 16 + (((lane >> 3) & 1) << 3);
                uint32_t off = (uint32_t)(n * RS + k) * 2;
                ldm4(bh[p], sB_hi + off);
                ldm4(bl[p], sB_lo + off);
            }
#pragma unroll
            for (int mf = 0; mf < 4; mf++)
#pragma unroll
                for (int nf = 0; nf < 4; nf++) {
                    const int p = nf >> 1, q = (nf & 1) * 2;
                    mma16816(acc[mf][nf], ah[mf], bh[p][q], bh[p][q + 1]);
                    mma16816(acc[mf][nf], ah[mf], bl[p][q], bl[p][q + 1]);
                    mma16816(acc[mf][nf], al[mf], bh[p][q], bh[p][q + 1]);
                }
        }
        __syncthreads();
    }

#pragma unroll
    for (int mf = 0; mf < 4; mf++)
#pragma unroll
        for (int nf = 0; nf < 4; nf++) {
            int row = bm + wm * 64 + mf * 16 + (lane >> 2);
            int col = bn + wn * 32 + nf * 8 + (lane & 3) * 2;
            *(float2*)&C[(size_t)row * CC + col] =
                make_float2(acc[mf][nf][0], acc[mf][nf][1]);
            *(float2*)&C[(size_t)(row + 8) * CC + col] =
                make_float2(acc[mf][nf][2], acc[mf][nf][3]);
        }
}

// ---------------- stage 2 (fast math) ----------------
__global__ __launch_bounds__(256) void k_stage2(
    const float* __restrict__ kraw_in,
    const float* __restrict__ hd,   const float* __restrict__ haaa,
    const float* __restrict__ hma,  const float* __restrict__ hmk,
    const float* __restrict__ hkkk, const float* __restrict__ gh,
    const float* __restrict__ td,   const float* __restrict__ dw2,
    const float* __restrict__ taa,  const float* __restrict__ aw2,
    const float* __restrict__ tmisca, const float* __restrict__ maw2,
    const float* __restrict__ tmisck, const float* __restrict__ mkw2,
    const float* __restrict__ kkkw2,  const float* __restrict__ gw2,
    float* __restrict__ decout, float* __restrict__ aout,
    float* __restrict__ kkout,  float* __restrict__ kout, float* __restrict__ gout) {
    const int t0 = blockIdx.x * 8, tid = threadIdx.x;
    __shared__ float shd[8][64];
    __shared__ float sh16[4][8][16];
    __shared__ float shg[8][128];
    for (int i = tid; i < 8 * 64; i += 256)
        shd[i >> 6][i & 63] = hd[(size_t)(t0 + (i >> 6)) * 64 + (i & 63)];
    for (int i = tid; i < 8 * 16; i += 256) {
        int rr = i >> 4, j = i & 15;
        sh16[0][rr][j] = haaa[(size_t)(t0 + rr) * 16 + j];
        sh16[1][rr][j] = hma [(size_t)(t0 + rr) * 16 + j];
        sh16[2][rr][j] = hmk [(size_t)(t0 + rr) * 16 + j];
        sh16[3][rr][j] = hkkk[(size_t)(t0 + rr) * 16 + j];
    }
    for (int i = tid; i < 8 * 128; i += 256)
        shg[i >> 7][i & 127] = gh[(size_t)(t0 + (i >> 7)) * 128 + (i & 127)];
    __syncthreads();

    for (int c = tid; c < CC; c += 256) {
        float ud[8], ua[8], uma[8], umk[8], ukk[8], ug[8];
#pragma unroll
        for (int rr = 0; rr < 8; rr++) { ud[rr]=0.f; ua[rr]=0.f; uma[rr]=0.f; umk[rr]=0.f; ukk[rr]=0.f; ug[rr]=0.f; }
#pragma unroll 8
        for (int j = 0; j < 64; j++) {
            float w = dw2[(size_t)j * CC + c];
#pragma unroll
            for (int rr = 0; rr < 8; rr++) ud[rr] = fmaf(shd[rr][j], w, ud[rr]);
        }
#pragma unroll 4
        for (int j = 0; j < 16; j++) {
            float w1 = aw2[(size_t)j * CC + c],  w2v = maw2[(size_t)j * CC + c];
            float w3 = mkw2[(size_t)j * CC + c], w4  = kkkw2[(size_t)j * CC + c];
#pragma unroll
            for (int rr = 0; rr < 8; rr++) {
                ua[rr]  = fmaf(sh16[0][rr][j], w1,  ua[rr]);
                uma[rr] = fmaf(sh16[1][rr][j], w2v, uma[rr]);
                umk[rr] = fmaf(sh16[2][rr][j], w3,  umk[rr]);
                ukk[rr] = fmaf(sh16[3][rr][j], w4,  ukk[rr]);
            }
        }
#pragma unroll 8
        for (int j = 0; j < 128; j++) {
            float w = gw2[(size_t)j * CC + c];
#pragma unroll
            for (int rr = 0; rr < 8; rr++) ug[rr] = fmaf(shg[rr][j], w, ug[rr]);
        }
        float tdv = td[c], taav = taa[c], tmav = tmisca[c], tmkv = tmisck[c];
#pragma unroll
        for (int rr = 0; rr < 8; rr++) {
            size_t idx = (size_t)(t0 + rr) * CC + c;
            float z  = tdv + ud[rr];
            float wv = -(fmaxf(-z, 0.f) + __logf(1.f + __expf(-fabsf(z)))) - 0.5f;
            decout[idx] = __expf(wv);
            float av  = __fdividef(1.f, 1.f + __expf(-(taav + ua[rr])));
            aout[idx] = av;
            float mav = __fdividef(1.f, 1.f + __expf(-(tmav + uma[rr])));
            float mkv = __fdividef(1.f, 1.f + __expf(-(tmkv + umk[rr])));
            float kr  = kraw_in[idx];
            kkout[idx] = kr + ukk[rr];
            float km = kr * (mav + av * (1.f - mav));
            km *= __expf(fminf(wv * mkv, 0.f));
            kout[idx] = km;
            gout[idx] = ug[rr];
        }
    }
}

// ---------------- kk norm ----------------
__global__ void k_kknorm(float* __restrict__ kk) {
    const int t = blockIdx.x, tid = threadIdx.x;
    const size_t base = (size_t)t * CC + tid * 8;
    float4 a = *(float4*)&kk[base];
    float4 b = *(float4*)&kk[base + 4];
    float ss = a.x*a.x + a.y*a.y + a.z*a.z + a.w*a.w
             + b.x*b.x + b.y*b.y + b.z*b.z + b.w*b.w;
    ss += __shfl_xor_sync(0xffffffffu, ss, 1);
    ss += __shfl_xor_sync(0xffffffffu, ss, 2);
    ss += __shfl_xor_sync(0xffffffffu, ss, 4);
    float inv = __fdividef(1.f, fmaxf(sqrtf(ss), 1e-12f));
    a.x *= inv; a.y *= inv; a.z *= inv; a.w *= inv;
    b.x *= inv; b.y *= inv; b.z *= inv; b.w *= inv;
    *(float4*)&kk[base]     = a;
    *(float4*)&kk[base + 4] = b;
}

// ---------------- WKV7 ----------------
__global__ __launch_bounds__(256) void k_wkv(
    const float* __restrict__ R, const float* __restrict__ Dec,
    const float* __restrict__ K, const float* __restrict__ Kk,
    const float* __restrict__ Asig, const float* __restrict__ V,
    float* __restrict__ Y) {
    const int h = blockIdx.x, rb = blockIdx.y, tid = threadIdx.x;
    const int il = tid >> 4, cg = tid & 15;
    const int i = rb * 16 + il;
    const int colbase = h * 64 + cg * 4;
    const int rowidx  = h * 64 + i;

    float4 s = make_float4(0.f, 0.f, 0.f, 0.f);
    float4 kkv = *(const float4*)&Kk[colbase];
    float4 dv  = *(const float4*)&Dec[colbase];
    float4 kv  = *(const float4*)&K[colbase];
    float4 rv  = *(const float4*)&R[colbase];
    float4 av  = *(const float4*)&Asig[colbase];
    float  vi  = V[rowidx];

    for (int t = 0; t < TT; t++) {
        const size_t nb = (size_t)((t + 1 < TT) ? (t + 1) : t) * CC;
        float4 kk2 = *(const float4*)&Kk[nb + colbase];
        float4 dv2 = *(const float4*)&Dec[nb + colbase];
        float4 kv2 = *(const float4*)&K[nb + colbase];
        float4 rv2 = *(const float4*)&R[nb + colbase];
        float4 av2 = *(const float4*)&Asig[nb + colbase];
        float  vi2 = V[nb + rowidx];

        float sa = s.x*kkv.x + s.y*kkv.y + s.z*kkv.z + s.w*kkv.w;
        sa += __shfl_xor_sync(0xffffffffu, sa, 1);
        sa += __shfl_xor_sync(0xffffffffu, sa, 2);
        sa += __shfl_xor_sync(0xffffffffu, sa, 4);
        sa += __shfl_xor_sync(0xffffffffu, sa, 8);
        sa = -sa;

        s.x = fmaf(vi, kv.x, fmaf(sa, kkv.x*av.x, s.x*dv.x));
        s.y = fmaf(vi, kv.y, fmaf(sa, kkv.y*av.y, s.y*dv.y));
        s.z = fmaf(vi, kv.z, fmaf(sa, kkv.z*av.z, s.z*dv.z));
        s.w = fmaf(vi, kv.w, fmaf(sa, kkv.w*av.w, s.w*dv.w));

        float o = s.x*rv.x + s.y*rv.y + s.z*rv.z + s.w*rv.w;
        o += __shfl_xor_sync(0xffffffffu, o, 1);
        o += __shfl_xor_sync(0xffffffffu, o, 2);
        o += __shfl_xor_sync(0xffffffffu, o, 4);
        o += __shfl_xor_sync(0xffffffffu, o, 8);
        if (cg == 0) Y[(size_t)t * CC + rowidx] = o;

        kkv = kk2; dv = dv2; kv = kv2; rv = rv2; av = av2; vi = vi2;
    }
}

// ---------------- groupnorm + bonus + gate ----------------
__global__ __launch_bounds__(512) void k_gn(
    const float* __restrict__ Yin, const float* __restrict__ R,
    const float* __restrict__ K,   const float* __restrict__ V,
    const float* __restrict__ G,   const float* __restrict__ faaaa,
    const float* __restrict__ lnw, const float* __restrict__ lnb,
    float* __restrict__ Yout) {
    const int t = blockIdx.x, tid = threadIdx.x;
    const int c = tid * 4;
    const size_t idx = (size_t)t * CC + c;
    float4 y  = *(const float4*)&Yin[idx];
    float4 r4 = *(const float4*)&R[idx];
    float4 k4 = *(const float4*)&K[idx];
    float4 v4 = *(const float4*)&V[idx];
    float4 g4 = *(const float4*)&G[idx];
    float4 f4 = *(const float4*)&faaaa[c];
    float4 w4 = *(const float4*)&lnw[c];
    float4 b4 = *(const float4*)&lnb[c];

    float s1 = y.x + y.y + y.z + y.w;
    float s2 = y.x*y.x + y.y*y.y + y.z*y.z + y.w*y.w;
    float s3 = r4.x*k4.x*f4.x + r4.y*k4.y*f4.y + r4.z*k4.z*f4.z + r4.w*k4.w*f4.w;
#pragma unroll
    for (int m = 1; m <= 8; m <<= 1) {
        s1 += __shfl_xor_sync(0xffffffffu, s1, m);
        s2 += __shfl_xor_sync(0xffffffffu, s2, m);
        s3 += __shfl_xor_sync(0xffffffffu, s3, m);
    }
    float mu  = s1 * (1.f / 64.f);
    float var = s2 * (1.f / 64.f) - mu * mu;
    float rs  = rsqrtf(var + EPSGN);
    float4 o;
    o.x = (fmaf((y.x - mu) * rs, w4.x, b4.x) + s3 * v4.x) * g4.x;
    o.y = (fmaf((y.y - mu) * rs, w4.y, b4.y) + s3 * v4.y) * g4.y;
    o.z = (fmaf((y.z - mu) * rs, w4.z, b4.z) + s3 * v4.z) * g4.z;
    o.w = (fmaf((y.w - mu) * rs, w4.w, b4.w) + s3 * v4.w) * g4.w;
    *(float4*)&Yout[idx] = o;
}

// ---------------------------------------------------------------------------
extern "C" void kernel_launch(void* const* d_in, const int* in_sizes, int n_in,
                              void* d_out, int out_size) {
    const float* x      = (const float*)d_in[0];
    const float* Wq     = (const float*)d_in[1];
    const float* Wk     = (const float*)d_in[2];
    const float* Wv     = (const float*)d_in[3];
    const float* Wo     = (const float*)d_in[4];
    const float* tmx    = (const float*)d_in[5];
    const float* tmrg   = (const float*)d_in[6];
    const float* tmwa   = (const float*)d_in[7];
    const float* tmk    = (const float*)d_in[8];
    const float* tmv    = (const float*)d_in[9];
    const float* maa_w1 = (const float*)d_in[10];
    const float* maa_w2 = (const float*)d_in[11];
    const float* tdecay = (const float*)d_in[12];
    const float* dw1    = (const float*)d_in[13];
    const float* dw2    = (const float*)d_in[14];
    const float* taaaaa = (const float*)d_in[15];
    const float* aaa_w1 = (const float*)d_in[16];
    const float* aaa_w2 = (const float*)d_in[17];
    const float* kkk_w1 = (const float*)d_in[18];
    const float* kkk_w2 = (const float*)d_in[19];
    const float* gate_w1 = (const float*)d_in[20];
    const float* gate_w2 = (const float*)d_in[21];
    const float* tmisca = (const float*)d_in[22];
    const float* ma_w1  = (const float*)d_in[23];
    const float* ma_w2  = (const float*)d_in[24];
    const float* tmisck = (const float*)d_in[25];
    const float* mk_w1  = (const float*)d_in[26];
    const float* mk_w2  = (const float*)d_in[27];
    const float* faaaa  = (const float*)d_in[28];
    const float* lnw    = (const float*)d_in[29];
    const float* lnb    = (const float*)d_in[30];
    float* out = (float*)d_out;

    float* S = nullptr;
    cudaGetSymbolAddress((void**)&S, g_scratch);
    __nv_bfloat16* BF = nullptr;
    cudaGetSymbolAddress((void**)&BF, g_bf);

    float* dxp  = S + O_DXP;  float* xxx  = S + O_XXX;
    float* xrg  = S + O_XRG;  float* xwa  = S + O_XWA;
    float* xk   = S + O_XK;   float* xv   = S + O_XV;
    float* R    = S + O_R;    float* Kraw = S + O_KRAW;
    float* V    = S + O_V;    float* Dec  = S + O_DEC;
    float* A    = S + O_A;    float* KK   = S + O_KK;
    float* K    = S + O_K;    float* G    = S + O_G;
    float* Y    = S + O_Y;    float* YM   = S + O_YM;
    float* hmix = S + O_HMIX; float* gh   = S + O_GH;
    float* hd   = S + O_HD;   float* haaa = S + O_HAAA;
    float* hma  = S + O_HMA;  float* hmk  = S + O_HMK;
    float* hkkk = S + O_HKKK;

    __nv_bfloat16* WThi = BF;
    __nv_bfloat16* WTlo = BF + (size_t)CC * CC;
    __nv_bfloat16* Ahi  = BF + 2ull * CC * CC;
    __nv_bfloat16* Alo  = Ahi + (size_t)TT * CC;

    cudaFuncSetAttribute(k_bigmm, cudaFuncAttributeMaxDynamicSharedMemorySize, GM_SMEM);

    // proj smem sizes: 2*(64*NN + 512)*4 bytes
    const int PS128 = 2 * (64 * 128 + 512) * 4;
    const int PS64  = 2 * (64 * 64  + 512) * 4;
    const int PS32  = 2 * (64 * 32  + 512) * 4;
    cudaFuncSetAttribute((const void*)k_proj<128,128,1,0>, cudaFuncAttributeMaxDynamicSharedMemorySize, PS128);
    cudaFuncSetAttribute((const void*)k_proj<64,64,1,0>,   cudaFuncAttributeMaxDynamicSharedMemorySize, PS64);
    cudaFuncSetAttribute((const void*)k_proj<32,16,0,0>,   cudaFuncAttributeMaxDynamicSharedMemorySize, PS32);
    cudaFuncSetAttribute((const void*)k_proj<32,16,0,1>,   cudaFuncAttributeMaxDynamicSharedMemorySize, PS32);

    dim3 wg(64, 64);
    dim3 wb(32, 8);
    dim3 mg(CC / 128, TT / 128);

    // 1
    k_tokshift<<<TC / 256, 256>>>(x, tmx, dxp, xxx);
    // 2
    k_proj<128,128,1,0><<<TT / 8, 256, PS128>>>(xxx, maa_w1, maa_w1, hmix, hmix);
    // 3
    k_mix_apply<<<dim3(CC / 128, TT / 8, 4), 128>>>(x, dxp, hmix, maa_w2,
                                                    tmrg, tmwa, tmk, tmv,
                                                    xrg, xwa, xk, xv);
    // 4, 5, 6 (ncu captures launch 6 = first k_bigmm)
    k_wprep<<<wg, wb>>>(Wq, WThi, WTlo);
    k_aprep<<<TC / 256, 256>>>(xrg, Ahi, Alo);
    k_bigmm<<<mg, 256, GM_SMEM>>>(Ahi, Alo, WThi, WTlo, R);

    k_wprep<<<wg, wb>>>(Wk, WThi, WTlo);
    k_aprep<<<TC / 256, 256>>>(xk, Ahi, Alo);
    k_bigmm<<<mg, 256, GM_SMEM>>>(Ahi, Alo, WThi, WTlo, Kraw);

    k_wprep<<<wg, wb>>>(Wv, WThi, WTlo);
    k_aprep<<<TC / 256, 256>>>(xv, Ahi, Alo);
    k_bigmm<<<mg, 256, GM_SMEM>>>(Ahi, Alo, WThi, WTlo, V);

    k_proj<128,128,1,0><<<TT / 8, 256, PS128>>>(xrg, gate_w1, gate_w1, gh, gh);
    k_proj<64,64,1,0>  <<<TT / 8, 256, PS64 >>>(xwa, dw1, dw1, hd, hd);
    k_proj<32,16,0,0>  <<<TT / 8, 256, PS32 >>>(xwa, aaa_w1, ma_w1, haaa, hma);
    k_proj<32,16,0,1>  <<<TT / 8, 256, PS32 >>>(xk,  mk_w1, kkk_w1, hmk, hkkk);

    k_stage2<<<TT / 8, 256>>>(Kraw, hd, haaa, hma, hmk, hkkk, gh,
                              tdecay, dw2, taaaaa, aaa_w2, tmisca, ma_w2,
                              tmisck, mk_w2, kkk_w2, gate_w2,
                              Dec, A, KK, K, G);
    k_kknorm<<<TT, 256>>>(KK);
    k_wkv<<<dim3(HH, 4), 256>>>(R, Dec, K, KK, A, V, Y);
    k_gn<<<TT, 512>>>(Y, R, K, V, G, faaaa, lnw, lnb, YM);

    k_wprep<<<wg, wb>>>(Wo, WThi, WTlo);
    k_aprep<<<TC / 256, 256>>>(YM, Ahi, Alo);
    k_bigmm<<<mg, 256, GM_SMEM>>>(Ahi, Alo, WThi, WTlo, out);
}

// round 6
// speedup vs baseline: 2.4267x; 1.0738x over previous
#include <cuda_runtime.h>
#include <cuda_bf16.h>
#include <math.h>
#include <stdint.h>

#define TT 1024
#define CC 2048
#define HH 32
#define TC (TT*CC)
#define EPSGN 0.00064f

// ---------------- scratch ----------------
__device__ __align__(128) float g_scratch[16ull*TC + 2ull*TT*128 + (size_t)TT*64 + 4ull*TT*16];
// 4 weights hi/lo + 4 activations hi/lo
__device__ __align__(128) __nv_bfloat16 g_bf[8ull*CC*CC + 8ull*TT*CC];

#define O_DXP   ((size_t)0*TC)
#define O_XXX   ((size_t)1*TC)
#define O_XRG   ((size_t)2*TC)
#define O_XWA   ((size_t)3*TC)
#define O_XK    ((size_t)4*TC)
#define O_XV    ((size_t)5*TC)
#define O_R     ((size_t)6*TC)
#define O_KRAW  ((size_t)7*TC)
#define O_V     ((size_t)8*TC)
#define O_DEC   ((size_t)9*TC)
#define O_A     ((size_t)10*TC)
#define O_KK    ((size_t)11*TC)
#define O_K     ((size_t)12*TC)
#define O_G     ((size_t)13*TC)
#define O_Y     ((size_t)14*TC)
#define O_HMIX  ((size_t)16*TC)
#define O_GH    (O_HMIX + (size_t)TT*128)
#define O_HD    (O_GH   + (size_t)TT*128)
#define O_HAAA  (O_HD   + (size_t)TT*64)
#define O_HMA   (O_HAAA + (size_t)TT*16)
#define O_HMK   (O_HMA  + (size_t)TT*16)
#define O_HKKK  (O_HMK  + (size_t)TT*16)

// ---------------- helpers ----------------
__device__ __forceinline__ uint32_t smem_u32(const void* p) {
    uint32_t a;
    asm("{ .reg .u64 t; cvta.to.shared.u64 t, %1; cvt.u32.u64 %0, t; }" : "=r"(a) : "l"(p));
    return a;
}
__device__ __forceinline__ void ldm4(uint32_t r[4], uint32_t a) {
    asm volatile("ldmatrix.sync.aligned.m8n8.x4.shared.b16 {%0,%1,%2,%3}, [%4];"
                 : "=r"(r[0]), "=r"(r[1]), "=r"(r[2]), "=r"(r[3]) : "r"(a));
}
__device__ __forceinline__ void mma16816(float c[4], const uint32_t a[4], uint32_t b0, uint32_t b1) {
    asm volatile("mma.sync.aligned.m16n8k16.row.col.f32.bf16.bf16.f32 "
                 "{%0,%1,%2,%3},{%4,%5,%6,%7},{%8,%9},{%0,%1,%2,%3};"
                 : "+f"(c[0]), "+f"(c[1]), "+f"(c[2]), "+f"(c[3])
                 : "r"(a[0]), "r"(a[1]), "r"(a[2]), "r"(a[3]), "r"(b0), "r"(b1));
}
#define CPA16(dst, src) asm volatile("cp.async.ca.shared.global [%0], [%1], 16;" :: "r"(dst), "l"(src))
#define CPA4(dst, src)  asm volatile("cp.async.ca.shared.global [%0], [%1], 4;"  :: "r"(dst), "l"(src))
#define CPA_COMMIT() asm volatile("cp.async.commit_group;" ::: "memory")

// ---------------- k_init: tokshift (blocks 0..8191) + wprep x4 (blocks 8192..24575) ----
__global__ void k_init(const float* __restrict__ x, const float* __restrict__ maa_x,
                       float* __restrict__ dxp, float* __restrict__ xxx,
                       const float* __restrict__ Wq, const float* __restrict__ Wk,
                       const float* __restrict__ Wv, const float* __restrict__ Wo,
                       __nv_bfloat16* __restrict__ BF) {
    const int bid = blockIdx.x, tid = threadIdx.x;
    if (bid < 8192) {
        int idx = bid * 256 + tid;
        int t = idx >> 11, c = idx & (CC - 1);
        float xv = x[idx];
        float pv = (t > 0) ? x[idx - CC] : 0.0f;
        float dx = pv - xv;
        dxp[idx] = dx;
        xxx[idx] = fmaf(dx, maa_x[c], xv);
        return;
    }
    __shared__ float tl[32][33];
    const int wb = bid - 8192;
    const int widx = wb >> 12;
    const int tile = wb & 4095;
    const float* W = (widx == 0) ? Wq : (widx == 1) ? Wk : (widx == 2) ? Wv : Wo;
    __nv_bfloat16* Thi = BF + (size_t)widx * 2 * CC * CC;
    __nv_bfloat16* Tlo = Thi + (size_t)CC * CC;
    const int n0 = (tile & 63) * 32, k0 = (tile >> 6) * 32;
    const int tx = tid & 31, ty = tid >> 5;
#pragma unroll
    for (int j = 0; j < 4; j++)
        tl[ty + j * 8][tx] = W[(size_t)(k0 + ty + j * 8) * CC + n0 + tx];
    __syncthreads();
#pragma unroll
    for (int j = 0; j < 4; j++) {
        float v = tl[tx][ty + j * 8];
        __nv_bfloat16 h = __float2bfloat16(v);
        size_t o = (size_t)(n0 + ty + j * 8) * CC + k0 + tx;
        Thi[o] = h;
        Tlo[o] = __float2bfloat16(v - __bfloat162float(h));
    }
}

// ---------------- k_proj ----------------
template <int NN, int SPLIT, int ACT0, int ACT1>
__global__ __launch_bounds__(256) void k_proj(const float* __restrict__ A,
                                              const float* __restrict__ W0,
                                              const float* __restrict__ W1,
                                              float* __restrict__ out0,
                                              float* __restrict__ out1) {
    constexpr int G = 256 / NN;
    constexpr int R = 8 / G;
    constexpr int WCH = 64 * NN;
    extern __shared__ __align__(16) float psm[];
    float* Ws = psm;
    float* As = psm + 2 * WCH;
    const uint32_t ws_b = smem_u32(Ws);
    const uint32_t as_b = smem_u32(As);

    const int tid = threadIdx.x;
    const int n = tid % NN, g = tid / NN;
    const int r0 = blockIdx.x * 8;

    auto load_stage = [&](int kc, int stg) {
#pragma unroll
        for (int j = 0; j < WCH / 1024; j++) {
            int i = (tid + j * 256) * 4;
            int row = i / NN, col = i % NN;
            const float* src = (col < SPLIT)
                ? (W0 + (size_t)(kc + row) * SPLIT + col)
                : (W1 + (size_t)(kc + row) * (NN - SPLIT) + (col - SPLIT));
            CPA16(ws_b + (uint32_t)(stg * WCH + i) * 4, src);
        }
#pragma unroll
        for (int j = 0; j < 2; j++) {
            int i = tid + j * 256;
            int row = i >> 6, k = i & 63;
            CPA4(as_b + (uint32_t)(stg * 512 + k * 8 + row) * 4,
                 A + (size_t)(r0 + row) * CC + kc + k);
        }
        CPA_COMMIT();
    };

    float acc[R];
#pragma unroll
    for (int i = 0; i < R; i++) acc[i] = 0.f;

    load_stage(0, 0);
    for (int ch = 0; ch < 32; ch++) {
        const int b = ch & 1;
        if (ch + 1 < 32) {
            load_stage((ch + 1) * 64, b ^ 1);
            asm volatile("cp.async.wait_group 1;" ::: "memory");
        } else {
            asm volatile("cp.async.wait_group 0;" ::: "memory");
        }
        __syncthreads();
        const float* ws = Ws + b * WCH;
        const float* as = As + b * 512;
#pragma unroll 8
        for (int k = 0; k < 64; k++) {
            float wv = ws[k * NN + n];
            if (R == 4) {
                float4 a4 = *(const float4*)&as[k * 8 + g * 4];
                acc[0] = fmaf(a4.x, wv, acc[0]);
                acc[1] = fmaf(a4.y, wv, acc[1]);
                acc[2] = fmaf(a4.z, wv, acc[2]);
                acc[3] = fmaf(a4.w, wv, acc[3]);
            } else if (R == 2) {
                float2 a2 = *(const float2*)&as[k * 8 + g * 2];
                acc[0] = fmaf(a2.x, wv, acc[0]);
                acc[1] = fmaf(a2.y, wv, acc[1]);
            } else {
                acc[0] = fmaf(as[k * 8 + g], wv, acc[0]);
            }
        }
        __syncthreads();
    }

#pragma unroll
    for (int i = 0; i < R; i++) {
        int row = r0 + g * R + i;
        float v = acc[i];
        if (n < SPLIT) {
            if (ACT0) v = tanhf(v);
            out0[(size_t)row * SPLIT + n] = v;
        } else {
            if (ACT1) v = tanhf(v);
            out1[(size_t)row * (NN - SPLIT) + (n - SPLIT)] = v;
        }
    }
}

// ---------------- mix apply (+ bf16 hi/lo emission for xrg/xk/xv) ----------------
__global__ void k_mix_apply(const float* __restrict__ x, const float* __restrict__ dxp,
                            const float* __restrict__ hmix, const float* __restrict__ w2full,
                            const float* __restrict__ tm0, const float* __restrict__ tm1,
                            const float* __restrict__ tm2, const float* __restrict__ tm3,
                            float* __restrict__ o0, float* __restrict__ o1,
                            float* __restrict__ o2, float* __restrict__ o3,
                            __nv_bfloat16* __restrict__ bh0, __nv_bfloat16* __restrict__ bl0,
                            __nv_bfloat16* __restrict__ bh2, __nv_bfloat16* __restrict__ bl2,
                            __nv_bfloat16* __restrict__ bh3, __nv_bfloat16* __restrict__ bl3) {
    const int f = blockIdx.z, t0 = blockIdx.y * 8;
    const int c = blockIdx.x * 128 + threadIdx.x;
    __shared__ float hm[8][32];
    for (int i = threadIdx.x; i < 8 * 32; i += 128) {
        int tt = i >> 5, d = i & 31;
        hm[tt][d] = hmix[(size_t)(t0 + tt) * 128 + f * 32 + d];
    }
    __syncthreads();
    const float* w2 = w2full + (size_t)f * 32 * CC;
    float acc[8];
#pragma unroll
    for (int i = 0; i < 8; i++) acc[i] = 0.f;
#pragma unroll 8
    for (int d = 0; d < 32; d++) {
        float wv = w2[(size_t)d * CC + c];
#pragma unroll
        for (int tt = 0; tt < 8; tt++) acc[tt] = fmaf(hm[tt][d], wv, acc[tt]);
    }
    const float* tm  = (f == 0) ? tm0 : (f == 1) ? tm1 : (f == 2) ? tm2 : tm3;
    float*       out = (f == 0) ? o0  : (f == 1) ? o1  : (f == 2) ? o2  : o3;
    __nv_bfloat16* ph = (f == 0) ? bh0 : (f == 2) ? bh2 : (f == 3) ? bh3 : nullptr;
    __nv_bfloat16* pl = (f == 0) ? bl0 : (f == 2) ? bl2 : (f == 3) ? bl3 : nullptr;
    float tmv = tm[c];
#pragma unroll
    for (int tt = 0; tt < 8; tt++) {
        size_t idx = (size_t)(t0 + tt) * CC + c;
        float v = fmaf(dxp[idx], tmv + acc[tt], x[idx]);
        out[idx] = v;
        if (f != 1) {
            __nv_bfloat16 h = __float2bfloat16(v);
            ph[idx] = h;
            pl[idx] = __float2bfloat16(v - __bfloat162float(h));
        }
    }
}

// ---------------- mma.sync split-bf16 GEMM (K-chunk 64, 2-stage) ----------------
#define RS 72
#define TILE_H (128 * RS)
#define STAGE_H (4 * TILE_H)
#define GM_SMEM (2 * STAGE_H * 2)
__global__ __launch_bounds__(256) void k_bigmm(
    const __nv_bfloat16* __restrict__ Ahi, const __nv_bfloat16* __restrict__ Alo,
    const __nv_bfloat16* __restrict__ Bhi, const __nv_bfloat16* __restrict__ Blo,
    float* __restrict__ C) {
    extern __shared__ __align__(16) __nv_bfloat16 sm[];
    const int tid = threadIdx.x, wid = tid >> 5, lane = tid & 31;
    const int bn = blockIdx.x * 128, bm = blockIdx.y * 128;
    const int wm = wid & 1, wn = wid >> 1;
    const uint32_t sb = smem_u32(sm);

    const __nv_bfloat16* gsrc[4] = {
        Ahi + (size_t)bm * CC, Alo + (size_t)bm * CC,
        Bhi + (size_t)bn * CC, Blo + (size_t)bn * CC };

    float acc[4][4][4];
#pragma unroll
    for (int a = 0; a < 4; a++)
#pragma unroll
        for (int b = 0; b < 4; b++)
#pragma unroll
            for (int c = 0; c < 4; c++) acc[a][b][c] = 0.f;

    const int lr = tid >> 3, ls = tid & 7;   // loader: 32 rows x 8 16B-segs
    auto load_stage = [&](int kc, int stg) {
#pragma unroll
        for (int tl = 0; tl < 4; tl++) {
            const __nv_bfloat16* s = gsrc[tl] + kc;
            uint32_t d = sb + (uint32_t)(stg * STAGE_H + tl * TILE_H) * 2;
#pragma unroll
            for (int j = 0; j < 4; j++) {
                int rr = lr + j * 32;
                CPA16(d + (uint32_t)(rr * RS + ls * 8) * 2, s + (size_t)rr * CC + ls * 8);
            }
        }
        CPA_COMMIT();
    };

    const int KT = CC / 64;   // 32 chunks
    load_stage(0, 0);

    for (int kt = 0; kt < KT; kt++) {
        const int stg = kt & 1;
        if (kt + 1 < KT) {
            load_stage((kt + 1) * 64, stg ^ 1);
            asm volatile("cp.async.wait_group 1;" ::: "memory");
        } else {
            asm volatile("cp.async.wait_group 0;" ::: "memory");
        }
        __syncthreads();

        const uint32_t sA_hi = sb + (uint32_t)(stg * STAGE_H + 0 * TILE_H) * 2;
        const uint32_t sA_lo = sb + (uint32_t)(stg * STAGE_H + 1 * TILE_H) * 2;
        const uint32_t sB_hi = sb + (uint32_t)(stg * STAGE_H + 2 * TILE_H) * 2;
        const uint32_t sB_lo = sb + (uint32_t)(stg * STAGE_H + 3 * TILE_H) * 2;

#pragma unroll
        for (int ks = 0; ks < 4; ks++) {
            uint32_t ah[4][4], al[4][4], bh[2][4], bl[2][4];
#pragma unroll
            for (int mf = 0; mf < 4; mf++) {
                int row = wm * 64 + mf * 16 + (lane & 15);
                int col = ks * 16 + ((lane >> 4) << 3);
                uint32_t off = (uint32_t)(row * RS + col) * 2;
                ldm4(ah[mf], sA_hi + off);
                ldm4(al[mf], sA_lo + off);
            }
#pragma unroll
            for (int p = 0; p < 2; p++) {
                int n = wn * 32 + p * 16 + ((lane >> 4) << 3) + (lane & 7);
                int k = ks * 16 + (((lane >> 3) & 1) << 3);
                uint32_t off = (uint32_t)(n * RS + k) * 2;
                ldm4(bh[p], sB_hi + off);
                ldm4(bl[p], sB_lo + off);
            }
#pragma unroll
            for (int mf = 0; mf < 4; mf++)
#pragma unroll
                for (int nf = 0; nf < 4; nf++) {
                    const int p = nf >> 1, q = (nf & 1) * 2;
                    mma16816(acc[mf][nf], ah[mf], bh[p][q], bh[p][q + 1]);
                    mma16816(acc[mf][nf], ah[mf], bl[p][q], bl[p][q + 1]);
                    mma16816(acc[mf][nf], al[mf], bh[p][q], bh[p][q + 1]);
                }
        }
        __syncthreads();
    }

#pragma unroll
    for (int mf = 0; mf < 4; mf++)
#pragma unroll
        for (int nf = 0; nf < 4; nf++) {
            int row = bm + wm * 64 + mf * 16 + (lane >> 2);
            int col = bn + wn * 32 + nf * 8 + (lane & 3) * 2;
            *(float2*)&C[(size_t)row * CC + col] =
                make_float2(acc[mf][nf][0], acc[mf][nf][1]);
            *(float2*)&C[(size_t)(row + 8) * CC + col] =
                make_float2(acc[mf][nf][2], acc[mf][nf][3]);
        }
}

// ---------------- stage 2 ----------------
__global__ __launch_bounds__(256) void k_stage2(
    const float* __restrict__ kraw_in,
    const float* __restrict__ hd,   const float* __restrict__ haaa,
    const float* __restrict__ hma,  const float* __restrict__ hmk,
    const float* __restrict__ hkkk, const float* __restrict__ gh,
    const float* __restrict__ td,   const float* __restrict__ dw2,
    const float* __restrict__ taa,  const float* __restrict__ aw2,
    const float* __restrict__ tmisca, const float* __restrict__ maw2,
    const float* __restrict__ tmisck, const float* __restrict__ mkw2,
    const float* __restrict__ kkkw2,  const float* __restrict__ gw2,
    float* __restrict__ decout, float* __restrict__ aout,
    float* __restrict__ kkout,  float* __restrict__ kout, float* __restrict__ gout) {
    const int t0 = blockIdx.x * 8, tid = threadIdx.x;
    __shared__ float shd[8][64];
    __shared__ float sh16[4][8][16];
    __shared__ float shg[8][128];
    for (int i = tid; i < 8 * 64; i += 256)
        shd[i >> 6][i & 63] = hd[(size_t)(t0 + (i >> 6)) * 64 + (i & 63)];
    for (int i = tid; i < 8 * 16; i += 256) {
        int rr = i >> 4, j = i & 15;
        sh16[0][rr][j] = haaa[(size_t)(t0 + rr) * 16 + j];
        sh16[1][rr][j] = hma [(size_t)(t0 + rr) * 16 + j];
        sh16[2][rr][j] = hmk [(size_t)(t0 + rr) * 16 + j];
        sh16[3][rr][j] = hkkk[(size_t)(t0 + rr) * 16 + j];
    }
    for (int i = tid; i < 8 * 128; i += 256)
        shg[i >> 7][i & 127] = gh[(size_t)(t0 + (i >> 7)) * 128 + (i & 127)];
    __syncthreads();

    for (int c = tid; c < CC; c += 256) {
        float ud[8], ua[8], uma[8], umk[8], ukk[8], ug[8];
#pragma unroll
        for (int rr = 0; rr < 8; rr++) { ud[rr]=0.f; ua[rr]=0.f; uma[rr]=0.f; umk[rr]=0.f; ukk[rr]=0.f; ug[rr]=0.f; }
#pragma unroll 8
        for (int j = 0; j < 64; j++) {
            float w = dw2[(size_t)j * CC + c];
#pragma unroll
            for (int rr = 0; rr < 8; rr++) ud[rr] = fmaf(shd[rr][j], w, ud[rr]);
        }
#pragma unroll 4
        for (int j = 0; j < 16; j++) {
            float w1 = aw2[(size_t)j * CC + c],  w2v = maw2[(size_t)j * CC + c];
            float w3 = mkw2[(size_t)j * CC + c], w4  = kkkw2[(size_t)j * CC + c];
#pragma unroll
            for (int rr = 0; rr < 8; rr++) {
                ua[rr]  = fmaf(sh16[0][rr][j], w1,  ua[rr]);
                uma[rr] = fmaf(sh16[1][rr][j], w2v, uma[rr]);
                umk[rr] = fmaf(sh16[2][rr][j], w3,  umk[rr]);
                ukk[rr] = fmaf(sh16[3][rr][j], w4,  ukk[rr]);
            }
        }
#pragma unroll 8
        for (int j = 0; j < 128; j++) {
            float w = gw2[(size_t)j * CC + c];
#pragma unroll
            for (int rr = 0; rr < 8; rr++) ug[rr] = fmaf(shg[rr][j], w, ug[rr]);
        }
        float tdv = td[c], taav = taa[c], tmav = tmisca[c], tmkv = tmisck[c];
#pragma unroll
        for (int rr = 0; rr < 8; rr++) {
            size_t idx = (size_t)(t0 + rr) * CC + c;
            float z  = tdv + ud[rr];
            float wv = -(fmaxf(-z, 0.f) + __logf(1.f + __expf(-fabsf(z)))) - 0.5f;
            decout[idx] = __expf(wv);
            float av  = __fdividef(1.f, 1.f + __expf(-(taav + ua[rr])));
            aout[idx] = av;
            float mav = __fdividef(1.f, 1.f + __expf(-(tmav + uma[rr])));
            float mkv = __fdividef(1.f, 1.f + __expf(-(tmkv + umk[rr])));
            float kr  = kraw_in[idx];
            kkout[idx] = kr + ukk[rr];
            float km = kr * (mav + av * (1.f - mav));
            km *= __expf(fminf(wv * mkv, 0.f));
            kout[idx] = km;
            gout[idx] = ug[rr];
        }
    }
}

// ---------------- kk norm ----------------
__global__ void k_kknorm(float* __restrict__ kk) {
    const int t = blockIdx.x, tid = threadIdx.x;
    const size_t base = (size_t)t * CC + tid * 8;
    float4 a = *(float4*)&kk[base];
    float4 b = *(float4*)&kk[base + 4];
    float ss = a.x*a.x + a.y*a.y + a.z*a.z + a.w*a.w
             + b.x*b.x + b.y*b.y + b.z*b.z + b.w*b.w;
    ss += __shfl_xor_sync(0xffffffffu, ss, 1);
    ss += __shfl_xor_sync(0xffffffffu, ss, 2);
    ss += __shfl_xor_sync(0xffffffffu, ss, 4);
    float inv = __fdividef(1.f, fmaxf(sqrtf(ss), 1e-12f));
    a.x *= inv; a.y *= inv; a.z *= inv; a.w *= inv;
    b.x *= inv; b.y *= inv; b.z *= inv; b.w *= inv;
    *(float4*)&kk[base]     = a;
    *(float4*)&kk[base + 4] = b;
}

// ---------------- WKV7 ----------------
__global__ __launch_bounds__(256) void k_wkv(
    const float* __restrict__ R, const float* __restrict__ Dec,
    const float* __restrict__ K, const float* __restrict__ Kk,
    const float* __restrict__ Asig, const float* __restrict__ V,
    float* __restrict__ Y) {
    const int h = blockIdx.x, rb = blockIdx.y, tid = threadIdx.x;
    const int il = tid >> 4, cg = tid & 15;
    const int i = rb * 16 + il;
    const int colbase = h * 64 + cg * 4;
    const int rowidx  = h * 64 + i;

    float4 s = make_float4(0.f, 0.f, 0.f, 0.f);
    float4 kkv = *(const float4*)&Kk[colbase];
    float4 dv  = *(const float4*)&Dec[colbase];
    float4 kv  = *(const float4*)&K[colbase];
    float4 rv  = *(const float4*)&R[colbase];
    float4 av  = *(const float4*)&Asig[colbase];
    float  vi  = V[rowidx];

    for (int t = 0; t < TT; t++) {
        const size_t nb = (size_t)((t + 1 < TT) ? (t + 1) : t) * CC;
        float4 kk2 = *(const float4*)&Kk[nb + colbase];
        float4 dv2 = *(const float4*)&Dec[nb + colbase];
        float4 kv2 = *(const float4*)&K[nb + colbase];
        float4 rv2 = *(const float4*)&R[nb + colbase];
        float4 av2 = *(const float4*)&Asig[nb + colbase];
        float  vi2 = V[nb + rowidx];

        float sa = s.x*kkv.x + s.y*kkv.y + s.z*kkv.z + s.w*kkv.w;
        sa += __shfl_xor_sync(0xffffffffu, sa, 1);
        sa += __shfl_xor_sync(0xffffffffu, sa, 2);
        sa += __shfl_xor_sync(0xffffffffu, sa, 4);
        sa += __shfl_xor_sync(0xffffffffu, sa, 8);
        sa = -sa;

        s.x = fmaf(vi, kv.x, fmaf(sa, kkv.x*av.x, s.x*dv.x));
        s.y = fmaf(vi, kv.y, fmaf(sa, kkv.y*av.y, s.y*dv.y));
        s.z = fmaf(vi, kv.z, fmaf(sa, kkv.z*av.z, s.z*dv.z));
        s.w = fmaf(vi, kv.w, fmaf(sa, kkv.w*av.w, s.w*dv.w));

        float o = s.x*rv.x + s.y*rv.y + s.z*rv.z + s.w*rv.w;
        o += __shfl_xor_sync(0xffffffffu, o, 1);
        o += __shfl_xor_sync(0xffffffffu, o, 2);
        o += __shfl_xor_sync(0xffffffffu, o, 4);
        o += __shfl_xor_sync(0xffffffffu, o, 8);
        if (cg == 0) Y[(size_t)t * CC + rowidx] = o;

        kkv = kk2; dv = dv2; kv = kv2; rv = rv2; av = av2; vi = vi2;
    }
}

// ---------------- groupnorm + bonus + gate -> bf16 hi/lo ----------------
__global__ __launch_bounds__(512) void k_gn(
    const float* __restrict__ Yin, const float* __restrict__ R,
    const float* __restrict__ K,   const float* __restrict__ V,
    const float* __restrict__ G,   const float* __restrict__ faaaa,
    const float* __restrict__ lnw, const float* __restrict__ lnb,
    __nv_bfloat16* __restrict__ ymhi, __nv_bfloat16* __restrict__ ymlo) {
    const int t = blockIdx.x, tid = threadIdx.x;
    const int c = tid * 4;
    const size_t idx = (size_t)t * CC + c;
    float4 y  = *(const float4*)&Yin[idx];
    float4 r4 = *(const float4*)&R[idx];
    float4 k4 = *(const float4*)&K[idx];
    float4 v4 = *(const float4*)&V[idx];
    float4 g4 = *(const float4*)&G[idx];
    float4 f4 = *(const float4*)&faaaa[c];
    float4 w4 = *(const float4*)&lnw[c];
    float4 b4 = *(const float4*)&lnb[c];

    float s1 = y.x + y.y + y.z + y.w;
    float s2 = y.x*y.x + y.y*y.y + y.z*y.z + y.w*y.w;
    float s3 = r4.x*k4.x*f4.x + r4.y*k4.y*f4.y + r4.z*k4.z*f4.z + r4.w*k4.w*f4.w;
#pragma unroll
    for (int m = 1; m <= 8; m <<= 1) {
        s1 += __shfl_xor_sync(0xffffffffu, s1, m);
        s2 += __shfl_xor_sync(0xffffffffu, s2, m);
        s3 += __shfl_xor_sync(0xffffffffu, s3, m);
    }
    float mu  = s1 * (1.f / 64.f);
    float var = s2 * (1.f / 64.f) - mu * mu;
    float rs  = rsqrtf(var + EPSGN);
    float o[4];
    o[0] = (fmaf((y.x - mu) * rs, w4.x, b4.x) + s3 * v4.x) * g4.x;
    o[1] = (fmaf((y.y - mu) * rs, w4.y, b4.y) + s3 * v4.y) * g4.y;
    o[2] = (fmaf((y.z - mu) * rs, w4.z, b4.z) + s3 * v4.z) * g4.z;
    o[3] = (fmaf((y.w - mu) * rs, w4.w, b4.w) + s3 * v4.w) * g4.w;
    __nv_bfloat16 hh[4], ll[4];
#pragma unroll
    for (int q = 0; q < 4; q++) {
        hh[q] = __float2bfloat16(o[q]);
        ll[q] = __float2bfloat16(o[q] - __bfloat162float(hh[q]));
    }
    *(uint2*)&ymhi[idx] = *(uint2*)hh;
    *(uint2*)&ymlo[idx] = *(uint2*)ll;
}

// ---------------------------------------------------------------------------
extern "C" void kernel_launch(void* const* d_in, const int* in_sizes, int n_in,
                              void* d_out, int out_size) {
    const float* x      = (const float*)d_in[0];
    const float* Wq     = (const float*)d_in[1];
    const float* Wk     = (const float*)d_in[2];
    const float* Wv     = (const float*)d_in[3];
    const float* Wo     = (const float*)d_in[4];
    const float* tmx    = (const float*)d_in[5];
    const float* tmrg   = (const float*)d_in[6];
    const float* tmwa   = (const float*)d_in[7];
    const float* tmk    = (const float*)d_in[8];
    const float* tmv    = (const float*)d_in[9];
    const float* maa_w1 = (const float*)d_in[10];
    const float* maa_w2 = (const float*)d_in[11];
    const float* tdecay = (const float*)d_in[12];
    const float* dw1    = (const float*)d_in[13];
    const float* dw2    = (const float*)d_in[14];
    const float* taaaaa = (const float*)d_in[15];
    const float* aaa_w1 = (const float*)d_in[16];
    const float* aaa_w2 = (const float*)d_in[17];
    const float* kkk_w1 = (const float*)d_in[18];
    const float* kkk_w2 = (const float*)d_in[19];
    const float* gate_w1 = (const float*)d_in[20];
    const float* gate_w2 = (const float*)d_in[21];
    const float* tmisca = (const float*)d_in[22];
    const float* ma_w1  = (const float*)d_in[23];
    const float* ma_w2  = (const float*)d_in[24];
    const float* tmisck = (const float*)d_in[25];
    const float* mk_w1  = (const float*)d_in[26];
    const float* mk_w2  = (const float*)d_in[27];
    const float* faaaa  = (const float*)d_in[28];
    const float* lnw    = (const float*)d_in[29];
    const float* lnb    = (const float*)d_in[30];
    float* out = (float*)d_out;

    float* S = nullptr;
    cudaGetSymbolAddress((void**)&S, g_scratch);
    __nv_bfloat16* BF = nullptr;
    cudaGetSymbolAddress((void**)&BF, g_bf);

    float* dxp  = S + O_DXP;  float* xxx  = S + O_XXX;
    float* xrg  = S + O_XRG;  float* xwa  = S + O_XWA;
    float* xk   = S + O_XK;   float* xv   = S + O_XV;
    float* R    = S + O_R;    float* Kraw = S + O_KRAW;
    float* V    = S + O_V;    float* Dec  = S + O_DEC;
    float* A    = S + O_A;    float* KK   = S + O_KK;
    float* K    = S + O_K;    float* G    = S + O_G;
    float* Y    = S + O_Y;
    float* hmix = S + O_HMIX; float* gh   = S + O_GH;
    float* hd   = S + O_HD;   float* haaa = S + O_HAAA;
    float* hma  = S + O_HMA;  float* hmk  = S + O_HMK;
    float* hkkk = S + O_HKKK;

    __nv_bfloat16* Wbuf[4][2];
    for (int i = 0; i < 4; i++) {
        Wbuf[i][0] = BF + (size_t)i * 2 * CC * CC;
        Wbuf[i][1] = Wbuf[i][0] + (size_t)CC * CC;
    }
    __nv_bfloat16* Abase = BF + 8ull * CC * CC;
    __nv_bfloat16* ArgH = Abase + 0ull * TC; __nv_bfloat16* ArgL = Abase + 1ull * TC;
    __nv_bfloat16* AkH  = Abase + 2ull * TC; __nv_bfloat16* AkL  = Abase + 3ull * TC;
    __nv_bfloat16* AvH  = Abase + 4ull * TC; __nv_bfloat16* AvL  = Abase + 5ull * TC;
    __nv_bfloat16* AyH  = Abase + 6ull * TC; __nv_bfloat16* AyL  = Abase + 7ull * TC;

    cudaFuncSetAttribute(k_bigmm, cudaFuncAttributeMaxDynamicSharedMemorySize, GM_SMEM);
    const int PS128 = 2 * (64 * 128 + 512) * 4;
    const int PS64  = 2 * (64 * 64  + 512) * 4;
    const int PS32  = 2 * (64 * 32  + 512) * 4;
    cudaFuncSetAttribute((const void*)k_proj<128,128,1,0>, cudaFuncAttributeMaxDynamicSharedMemorySize, PS128);
    cudaFuncSetAttribute((const void*)k_proj<64,64,1,0>,   cudaFuncAttributeMaxDynamicSharedMemorySize, PS64);
    cudaFuncSetAttribute((const void*)k_proj<32,16,0,0>,   cudaFuncAttributeMaxDynamicSharedMemorySize, PS32);
    cudaFuncSetAttribute((const void*)k_proj<32,16,0,1>,   cudaFuncAttributeMaxDynamicSharedMemorySize, PS32);

    dim3 mg(CC / 128, TT / 128);

    // 1: tokshift + all weight preps
    k_init<<<8192 + 16384, 256>>>(x, tmx, dxp, xxx, Wq, Wk, Wv, Wo, BF);
    // 2
    k_proj<128,128,1,0><<<TT / 8, 256, PS128>>>(xxx, maa_w1, maa_w1, hmix, hmix);
    // 3 (also emits bf16 xrg/xk/xv)
    k_mix_apply<<<dim3(CC / 128, TT / 8, 4), 128>>>(x, dxp, hmix, maa_w2,
                                                    tmrg, tmwa, tmk, tmv,
                                                    xrg, xwa, xk, xv,
                                                    ArgH, ArgL, AkH, AkL, AvH, AvL);
    // 4: CAPTURED by ncu
    k_bigmm<<<mg, 256, GM_SMEM>>>(ArgH, ArgL, Wbuf[0][0], Wbuf[0][1], R);
    // 5, 6
    k_bigmm<<<mg, 256, GM_SMEM>>>(AkH, AkL, Wbuf[1][0], Wbuf[1][1], Kraw);
    k_bigmm<<<mg, 256, GM_SMEM>>>(AvH, AvL, Wbuf[2][0], Wbuf[2][1], V);

    k_proj<128,128,1,0><<<TT / 8, 256, PS128>>>(xrg, gate_w1, gate_w1, gh, gh);
    k_proj<64,64,1,0>  <<<TT / 8, 256, PS64 >>>(xwa, dw1, dw1, hd, hd);
    k_proj<32,16,0,0>  <<<TT / 8, 256, PS32 >>>(xwa, aaa_w1, ma_w1, haaa, hma);
    k_proj<32,16,0,1>  <<<TT / 8, 256, PS32 >>>(xk,  mk_w1, kkk_w1, hmk, hkkk);

    k_stage2<<<TT / 8, 256>>>(Kraw, hd, haaa, hma, hmk, hkkk, gh,
                              tdecay, dw2, taaaaa, aaa_w2, tmisca, ma_w2,
                              tmisck, mk_w2, kkk_w2, gate_w2,
                              Dec, A, KK, K, G);
    k_kknorm<<<TT, 256>>>(KK);
    k_wkv<<<dim3(HH, 4), 256>>>(R, Dec, K, KK, A, V, Y);
    k_gn<<<TT, 512>>>(Y, R, K, V, G, faaaa, lnw, lnb, AyH, AyL);
    k_bigmm<<<mg, 256, GM_SMEM>>>(AyH, AyL, Wbuf[3][0], Wbuf[3][1], out);
}

// round 7
// speedup vs baseline: 3.2838x; 1.3532x over previous
#include <cuda_runtime.h>
#include <cuda_bf16.h>
#include <math.h>
#include <stdint.h>

#define TT 1024
#define CC 2048
#define HH 32
#define TC (TT*CC)
#define EPSGN 0.00064f

// ---------------- scratch ----------------
__device__ __align__(128) float g_scratch[16ull*TC + 2ull*TT*128 + (size_t)TT*64 + 4ull*TT*16];
// 4 weights hi/lo + 4 activations hi/lo
__device__ __align__(128) __nv_bfloat16 g_bf[8ull*CC*CC + 8ull*TT*CC];

#define O_DXP   ((size_t)0*TC)
#define O_XXX   ((size_t)1*TC)
#define O_XRG   ((size_t)2*TC)
#define O_XWA   ((size_t)3*TC)
#define O_XK    ((size_t)4*TC)
#define O_XV    ((size_t)5*TC)
#define O_R     ((size_t)6*TC)
#define O_KRAW  ((size_t)7*TC)
#define O_V     ((size_t)8*TC)
#define O_DEC   ((size_t)9*TC)
#define O_A     ((size_t)10*TC)
#define O_KK    ((size_t)11*TC)
#define O_K     ((size_t)12*TC)
#define O_G     ((size_t)13*TC)
#define O_Y     ((size_t)14*TC)
#define O_HMIX  ((size_t)16*TC)
#define O_GH    (O_HMIX + (size_t)TT*128)
#define O_HD    (O_GH   + (size_t)TT*128)
#define O_HAAA  (O_HD   + (size_t)TT*64)
#define O_HMA   (O_HAAA + (size_t)TT*16)
#define O_HMK   (O_HMA  + (size_t)TT*16)
#define O_HKKK  (O_HMK  + (size_t)TT*16)

// ---------------- helpers ----------------
__device__ __forceinline__ uint32_t smem_u32(const void* p) {
    uint32_t a;
    asm("{ .reg .u64 t; cvta.to.shared.u64 t, %1; cvt.u32.u64 %0, t; }" : "=r"(a) : "l"(p));
    return a;
}
__device__ __forceinline__ void ldm4(uint32_t r[4], uint32_t a) {
    asm volatile("ldmatrix.sync.aligned.m8n8.x4.shared.b16 {%0,%1,%2,%3}, [%4];"
                 : "=r"(r[0]), "=r"(r[1]), "=r"(r[2]), "=r"(r[3]) : "r"(a));
}
__device__ __forceinline__ void mma16816(float c[4], const uint32_t a[4], uint32_t b0, uint32_t b1) {
    asm volatile("mma.sync.aligned.m16n8k16.row.col.f32.bf16.bf16.f32 "
                 "{%0,%1,%2,%3},{%4,%5,%6,%7},{%8,%9},{%0,%1,%2,%3};"
                 : "+f"(c[0]), "+f"(c[1]), "+f"(c[2]), "+f"(c[3])
                 : "r"(a[0]), "r"(a[1]), "r"(a[2]), "r"(a[3]), "r"(b0), "r"(b1));
}
#define CPA16(dst, src) asm volatile("cp.async.ca.shared.global [%0], [%1], 16;" :: "r"(dst), "l"(src))
#define CPA4(dst, src)  asm volatile("cp.async.ca.shared.global [%0], [%1], 4;"  :: "r"(dst), "l"(src))
#define CPA_COMMIT() asm volatile("cp.async.commit_group;" ::: "memory")

// ---------------- k_init: tokshift (blocks 0..8191) + wprep x4 (blocks 8192..24575) ----
__global__ void k_init(const float* __restrict__ x, const float* __restrict__ maa_x,
                       float* __restrict__ dxp, float* __restrict__ xxx,
                       const float* __restrict__ Wq, const float* __restrict__ Wk,
                       const float* __restrict__ Wv, const float* __restrict__ Wo,
                       __nv_bfloat16* __restrict__ BF) {
    const int bid = blockIdx.x, tid = threadIdx.x;
    if (bid < 8192) {
        int idx = bid * 256 + tid;
        int t = idx >> 11, c = idx & (CC - 1);
        float xv = x[idx];
        float pv = (t > 0) ? x[idx - CC] : 0.0f;
        float dx = pv - xv;
        dxp[idx] = dx;
        xxx[idx] = fmaf(dx, maa_x[c], xv);
        return;
    }
    __shared__ float tl[32][33];
    const int wb = bid - 8192;
    const int widx = wb >> 12;
    const int tile = wb & 4095;
    const float* W = (widx == 0) ? Wq : (widx == 1) ? Wk : (widx == 2) ? Wv : Wo;
    __nv_bfloat16* Thi = BF + (size_t)widx * 2 * CC * CC;
    __nv_bfloat16* Tlo = Thi + (size_t)CC * CC;
    const int n0 = (tile & 63) * 32, k0 = (tile >> 6) * 32;
    const int tx = tid & 31, ty = tid >> 5;
#pragma unroll
    for (int j = 0; j < 4; j++)
        tl[ty + j * 8][tx] = W[(size_t)(k0 + ty + j * 8) * CC + n0 + tx];
    __syncthreads();
#pragma unroll
    for (int j = 0; j < 4; j++) {
        float v = tl[tx][ty + j * 8];
        __nv_bfloat16 h = __float2bfloat16(v);
        size_t o = (size_t)(n0 + ty + j * 8) * CC + k0 + tx;
        Thi[o] = h;
        Tlo[o] = __float2bfloat16(v - __bfloat162float(h));
    }
}

// ---------------- k_proj ----------------
template <int NN, int SPLIT, int ACT0, int ACT1>
__global__ __launch_bounds__(256) void k_proj(const float* __restrict__ A,
                                              const float* __restrict__ W0,
                                              const float* __restrict__ W1,
                                              float* __restrict__ out0,
                                              float* __restrict__ out1) {
    constexpr int G = 256 / NN;
    constexpr int R = 8 / G;
    constexpr int WCH = 64 * NN;
    extern __shared__ __align__(16) float psm[];
    float* Ws = psm;
    float* As = psm + 2 * WCH;
    const uint32_t ws_b = smem_u32(Ws);
    const uint32_t as_b = smem_u32(As);

    const int tid = threadIdx.x;
    const int n = tid % NN, g = tid / NN;
    const int r0 = blockIdx.x * 8;

    auto load_stage = [&](int kc, int stg) {
#pragma unroll
        for (int j = 0; j < WCH / 1024; j++) {
            int i = (tid + j * 256) * 4;
            int row = i / NN, col = i % NN;
            const float* src = (col < SPLIT)
                ? (W0 + (size_t)(kc + row) * SPLIT + col)
                : (W1 + (size_t)(kc + row) * (NN - SPLIT) + (col - SPLIT));
            CPA16(ws_b + (uint32_t)(stg * WCH + i) * 4, src);
        }
#pragma unroll
        for (int j = 0; j < 2; j++) {
            int i = tid + j * 256;
            int row = i >> 6, k = i & 63;
            CPA4(as_b + (uint32_t)(stg * 512 + k * 8 + row) * 4,
                 A + (size_t)(r0 + row) * CC + kc + k);
        }
        CPA_COMMIT();
    };

    float acc[R];
#pragma unroll
    for (int i = 0; i < R; i++) acc[i] = 0.f;

    load_stage(0, 0);
    for (int ch = 0; ch < 32; ch++) {
        const int b = ch & 1;
        if (ch + 1 < 32) {
            load_stage((ch + 1) * 64, b ^ 1);
            asm volatile("cp.async.wait_group 1;" ::: "memory");
        } else {
            asm volatile("cp.async.wait_group 0;" ::: "memory");
        }
        __syncthreads();
        const float* ws = Ws + b * WCH;
        const float* as = As + b * 512;
#pragma unroll 8
        for (int k = 0; k < 64; k++) {
            float wv = ws[k * NN + n];
            if (R == 4) {
                float4 a4 = *(const float4*)&as[k * 8 + g * 4];
                acc[0] = fmaf(a4.x, wv, acc[0]);
                acc[1] = fmaf(a4.y, wv, acc[1]);
                acc[2] = fmaf(a4.z, wv, acc[2]);
                acc[3] = fmaf(a4.w, wv, acc[3]);
            } else if (R == 2) {
                float2 a2 = *(const float2*)&as[k * 8 + g * 2];
                acc[0] = fmaf(a2.x, wv, acc[0]);
                acc[1] = fmaf(a2.y, wv, acc[1]);
            } else {
                acc[0] = fmaf(as[k * 8 + g], wv, acc[0]);
            }
        }
        __syncthreads();
    }

#pragma unroll
    for (int i = 0; i < R; i++) {
        int row = r0 + g * R + i;
        float v = acc[i];
        if (n < SPLIT) {
            if (ACT0) v = tanhf(v);
            out0[(size_t)row * SPLIT + n] = v;
        } else {
            if (ACT1) v = tanhf(v);
            out1[(size_t)row * (NN - SPLIT) + (n - SPLIT)] = v;
        }
    }
}

// ---------------- mix apply (+ bf16 hi/lo emission for xrg/xk/xv) ----------------
__global__ void k_mix_apply(const float* __restrict__ x, const float* __restrict__ dxp,
                            const float* __restrict__ hmix, const float* __restrict__ w2full,
                            const float* __restrict__ tm0, const float* __restrict__ tm1,
                            const float* __restrict__ tm2, const float* __restrict__ tm3,
                            float* __restrict__ o0, float* __restrict__ o1,
                            float* __restrict__ o2, float* __restrict__ o3,
                            __nv_bfloat16* __restrict__ bh0, __nv_bfloat16* __restrict__ bl0,
                            __nv_bfloat16* __restrict__ bh2, __nv_bfloat16* __restrict__ bl2,
                            __nv_bfloat16* __restrict__ bh3, __nv_bfloat16* __restrict__ bl3) {
    const int f = blockIdx.z, t0 = blockIdx.y * 8;
    const int c = blockIdx.x * 128 + threadIdx.x;
    __shared__ float hm[8][32];
    for (int i = threadIdx.x; i < 8 * 32; i += 128) {
        int tt = i >> 5, d = i & 31;
        hm[tt][d] = hmix[(size_t)(t0 + tt) * 128 + f * 32 + d];
    }
    __syncthreads();
    const float* w2 = w2full + (size_t)f * 32 * CC;
    float acc[8];
#pragma unroll
    for (int i = 0; i < 8; i++) acc[i] = 0.f;
#pragma unroll 8
    for (int d = 0; d < 32; d++) {
        float wv = w2[(size_t)d * CC + c];
#pragma unroll
        for (int tt = 0; tt < 8; tt++) acc[tt] = fmaf(hm[tt][d], wv, acc[tt]);
    }
    const float* tm  = (f == 0) ? tm0 : (f == 1) ? tm1 : (f == 2) ? tm2 : tm3;
    float*       out = (f == 0) ? o0  : (f == 1) ? o1  : (f == 2) ? o2  : o3;
    __nv_bfloat16* ph = (f == 0) ? bh0 : (f == 2) ? bh2 : (f == 3) ? bh3 : nullptr;
    __nv_bfloat16* pl = (f == 0) ? bl0 : (f == 2) ? bl2 : (f == 3) ? bl3 : nullptr;
    float tmv = tm[c];
#pragma unroll
    for (int tt = 0; tt < 8; tt++) {
        size_t idx = (size_t)(t0 + tt) * CC + c;
        float v = fmaf(dxp[idx], tmv + acc[tt], x[idx]);
        out[idx] = v;
        if (f != 1) {
            __nv_bfloat16 h = __float2bfloat16(v);
            ph[idx] = h;
            pl[idx] = __float2bfloat16(v - __bfloat162float(h));
        }
    }
}

// ---------------- mma.sync split-bf16 GEMM (K-chunk 64, 2-stage) ----------------
#define RS 72
#define TILE_H (128 * RS)
#define STAGE_H (4 * TILE_H)
#define GM_SMEM (2 * STAGE_H * 2)
__global__ __launch_bounds__(256) void k_bigmm(
    const __nv_bfloat16* __restrict__ Ahi, const __nv_bfloat16* __restrict__ Alo,
    const __nv_bfloat16* __restrict__ Bhi, const __nv_bfloat16* __restrict__ Blo,
    float* __restrict__ C) {
    extern __shared__ __align__(16) __nv_bfloat16 sm[];
    const int tid = threadIdx.x, wid = tid >> 5, lane = tid & 31;
    const int bn = blockIdx.x * 128, bm = blockIdx.y * 128;
    const int wm = wid & 1, wn = wid >> 1;
    const uint32_t sb = smem_u32(sm);

    const __nv_bfloat16* gsrc[4] = {
        Ahi + (size_t)bm * CC, Alo + (size_t)bm * CC,
        Bhi + (size_t)bn * CC, Blo + (size_t)bn * CC };

    float acc[4][4][4];
#pragma unroll
    for (int a = 0; a < 4; a++)
#pragma unroll
        for (int b = 0; b < 4; b++)
#pragma unroll
            for (int c = 0; c < 4; c++) acc[a][b][c] = 0.f;

    const int lr = tid >> 3, ls = tid & 7;
    auto load_stage = [&](int kc, int stg) {
#pragma unroll
        for (int tl = 0; tl < 4; tl++) {
            const __nv_bfloat16* s = gsrc[tl] + kc;
            uint32_t d = sb + (uint32_t)(stg * STAGE_H + tl * TILE_H) * 2;
#pragma unroll
            for (int j = 0; j < 4; j++) {
                int rr = lr + j * 32;
                CPA16(d + (uint32_t)(rr * RS + ls * 8) * 2, s + (size_t)rr * CC + ls * 8);
            }
        }
        CPA_COMMIT();
    };

    const int KT = CC / 64;
    load_stage(0, 0);

    for (int kt = 0; kt < KT; kt++) {
        const int stg = kt & 1;
        if (kt + 1 < KT) {
            load_stage((kt + 1) * 64, stg ^ 1);
            asm volatile("cp.async.wait_group 1;" ::: "memory");
        } else {
            asm volatile("cp.async.wait_group 0;" ::: "memory");
        }
        __syncthreads();

        const uint32_t sA_hi = sb + (uint32_t)(stg * STAGE_H + 0 * TILE_H) * 2;
        const uint32_t sA_lo = sb + (uint32_t)(stg * STAGE_H + 1 * TILE_H) * 2;
        const uint32_t sB_hi = sb + (uint32_t)(stg * STAGE_H + 2 * TILE_H) * 2;
        const uint32_t sB_lo = sb + (uint32_t)(stg * STAGE_H + 3 * TILE_H) * 2;

#pragma unroll
        for (int ks = 0; ks < 4; ks++) {
            uint32_t ah[4][4], al[4][4], bh[2][4], bl[2][4];
#pragma unroll
            for (int mf = 0; mf < 4; mf++) {
                int row = wm * 64 + mf * 16 + (lane & 15);
                int col = ks * 16 + ((lane >> 4) << 3);
                uint32_t off = (uint32_t)(row * RS + col) * 2;
                ldm4(ah[mf], sA_hi + off);
                ldm4(al[mf], sA_lo + off);
            }
#pragma unroll
            for (int p = 0; p < 2; p++) {
                int n = wn * 32 + p * 16 + ((lane >> 4) << 3) + (lane & 7);
                int k = ks * 16 + (((lane >> 3) & 1) << 3);
                uint32_t off = (uint32_t)(n * RS + k) * 2;
                ldm4(bh[p], sB_hi + off);
                ldm4(bl[p], sB_lo + off);
            }
#pragma unroll
            for (int mf = 0; mf < 4; mf++)
#pragma unroll
                for (int nf = 0; nf < 4; nf++) {
                    const int p = nf >> 1, q = (nf & 1) * 2;
                    mma16816(acc[mf][nf], ah[mf], bh[p][q], bh[p][q + 1]);
                    mma16816(acc[mf][nf], ah[mf], bl[p][q], bl[p][q + 1]);
                    mma16816(acc[mf][nf], al[mf], bh[p][q], bh[p][q + 1]);
                }
        }
        __syncthreads();
    }

#pragma unroll
    for (int mf = 0; mf < 4; mf++)
#pragma unroll
        for (int nf = 0; nf < 4; nf++) {
            int row = bm + wm * 64 + mf * 16 + (lane >> 2);
            int col = bn + wn * 32 + nf * 8 + (lane & 3) * 2;
            *(float2*)&C[(size_t)row * CC + col] =
                make_float2(acc[mf][nf][0], acc[mf][nf][1]);
            *(float2*)&C[(size_t)(row + 8) * CC + col] =
                make_float2(acc[mf][nf][2], acc[mf][nf][3]);
        }
}

// ---------------- stage 2 ----------------
__global__ __launch_bounds__(256) void k_stage2(
    const float* __restrict__ kraw_in,
    const float* __restrict__ hd,   const float* __restrict__ haaa,
    const float* __restrict__ hma,  const float* __restrict__ hmk,
    const float* __restrict__ hkkk, const float* __restrict__ gh,
    const float* __restrict__ td,   const float* __restrict__ dw2,
    const float* __restrict__ taa,  const float* __restrict__ aw2,
    const float* __restrict__ tmisca, const float* __restrict__ maw2,
    const float* __restrict__ tmisck, const float* __restrict__ mkw2,
    const float* __restrict__ kkkw2,  const float* __restrict__ gw2,
    float* __restrict__ decout, float* __restrict__ aout,
    float* __restrict__ kkout,  float* __restrict__ kout, float* __restrict__ gout) {
    const int t0 = blockIdx.x * 8, tid = threadIdx.x;
    __shared__ float shd[8][64];
    __shared__ float sh16[4][8][16];
    __shared__ float shg[8][128];
    for (int i = tid; i < 8 * 64; i += 256)
        shd[i >> 6][i & 63] = hd[(size_t)(t0 + (i >> 6)) * 64 + (i & 63)];
    for (int i = tid; i < 8 * 16; i += 256) {
        int rr = i >> 4, j = i & 15;
        sh16[0][rr][j] = haaa[(size_t)(t0 + rr) * 16 + j];
        sh16[1][rr][j] = hma [(size_t)(t0 + rr) * 16 + j];
        sh16[2][rr][j] = hmk [(size_t)(t0 + rr) * 16 + j];
        sh16[3][rr][j] = hkkk[(size_t)(t0 + rr) * 16 + j];
    }
    for (int i = tid; i < 8 * 128; i += 256)
        shg[i >> 7][i & 127] = gh[(size_t)(t0 + (i >> 7)) * 128 + (i & 127)];
    __syncthreads();

    for (int c = tid; c < CC; c += 256) {
        float ud[8], ua[8], uma[8], umk[8], ukk[8], ug[8];
#pragma unroll
        for (int rr = 0; rr < 8; rr++) { ud[rr]=0.f; ua[rr]=0.f; uma[rr]=0.f; umk[rr]=0.f; ukk[rr]=0.f; ug[rr]=0.f; }
#pragma unroll 8
        for (int j = 0; j < 64; j++) {
            float w = dw2[(size_t)j * CC + c];
#pragma unroll
            for (int rr = 0; rr < 8; rr++) ud[rr] = fmaf(shd[rr][j], w, ud[rr]);
        }
#pragma unroll 4
        for (int j = 0; j < 16; j++) {
            float w1 = aw2[(size_t)j * CC + c],  w2v = maw2[(size_t)j * CC + c];
            float w3 = mkw2[(size_t)j * CC + c], w4  = kkkw2[(size_t)j * CC + c];
#pragma unroll
            for (int rr = 0; rr < 8; rr++) {
                ua[rr]  = fmaf(sh16[0][rr][j], w1,  ua[rr]);
                uma[rr] = fmaf(sh16[1][rr][j], w2v, uma[rr]);
                umk[rr] = fmaf(sh16[2][rr][j], w3,  umk[rr]);
                ukk[rr] = fmaf(sh16[3][rr][j], w4,  ukk[rr]);
            }
        }
#pragma unroll 8
        for (int j = 0; j < 128; j++) {
            float w = gw2[(size_t)j * CC + c];
#pragma unroll
            for (int rr = 0; rr < 8; rr++) ug[rr] = fmaf(shg[rr][j], w, ug[rr]);
        }
        float tdv = td[c], taav = taa[c], tmav = tmisca[c], tmkv = tmisck[c];
#pragma unroll
        for (int rr = 0; rr < 8; rr++) {
            size_t idx = (size_t)(t0 + rr) * CC + c;
            float z  = tdv + ud[rr];
            float wv = -(fmaxf(-z, 0.f) + __logf(1.f + __expf(-fabsf(z)))) - 0.5f;
            decout[idx] = __expf(wv);
            float av  = __fdividef(1.f, 1.f + __expf(-(taav + ua[rr])));
            aout[idx] = av;
            float mav = __fdividef(1.f, 1.f + __expf(-(tmav + uma[rr])));
            float mkv = __fdividef(1.f, 1.f + __expf(-(tmkv + umk[rr])));
            float kr  = kraw_in[idx];
            kkout[idx] = kr + ukk[rr];
            float km = kr * (mav + av * (1.f - mav));
            km *= __expf(fminf(wv * mkv, 0.f));
            kout[idx] = km;
            gout[idx] = ug[rr];
        }
    }
}

// ---------------- kk norm ----------------
__global__ void k_kknorm(float* __restrict__ kk) {
    const int t = blockIdx.x, tid = threadIdx.x;
    const size_t base = (size_t)t * CC + tid * 8;
    float4 a = *(float4*)&kk[base];
    float4 b = *(float4*)&kk[base + 4];
    float ss = a.x*a.x + a.y*a.y + a.z*a.z + a.w*a.w
             + b.x*b.x + b.y*b.y + b.z*b.z + b.w*b.w;
    ss += __shfl_xor_sync(0xffffffffu, ss, 1);
    ss += __shfl_xor_sync(0xffffffffu, ss, 2);
    ss += __shfl_xor_sync(0xffffffffu, ss, 4);
    float inv = __fdividef(1.f, fmaxf(sqrtf(ss), 1e-12f));
    a.x *= inv; a.y *= inv; a.z *= inv; a.w *= inv;
    b.x *= inv; b.y *= inv; b.z *= inv; b.w *= inv;
    *(float4*)&kk[base]     = a;
    *(float4*)&kk[base + 4] = b;
}

// ---------------- WKV7: cp.async smem ring pipeline (8 stages, 7 lookahead) ----------
// stage layout (floats): [Dec 0..63][K 64..127][Kk 128..191][R 192..255][A 256..319][V 320..335]
__global__ __launch_bounds__(256) void k_wkv(
    const float* __restrict__ R, const float* __restrict__ Dec,
    const float* __restrict__ K, const float* __restrict__ Kk,
    const float* __restrict__ Asig, const float* __restrict__ V,
    float* __restrict__ Y) {
    __shared__ __align__(16) float ring[8 * 336];
    const int h = blockIdx.x, rb = blockIdx.y, tid = threadIdx.x;
    const int il = tid >> 4, cg = tid & 15;
    const int rowidx = h * 64 + rb * 16 + il;
    const uint32_t rbase = smem_u32(ring);

    // producer setup: 84 threads each own one 16B slice per stage
    const float* src0 = Dec + h * 64;  // dummy init
    uint32_t doff = 0;
    bool prod = (tid < 84);
    if (tid < 80) {
        int arr = tid >> 4, q = tid & 15;
        const float* base = (arr == 0) ? Dec : (arr == 1) ? K : (arr == 2) ? Kk
                          : (arr == 3) ? R : Asig;
        src0 = base + h * 64 + q * 4;
        doff = (uint32_t)(arr * 64 + q * 4) * 4;
    } else if (tid < 84) {
        src0 = V + h * 64 + rb * 16 + (tid - 80) * 4;
        doff = (uint32_t)(320 + (tid - 80) * 4) * 4;
    }

    auto issue = [&](int t) {
        if (prod) CPA16(rbase + (uint32_t)((t & 7) * 1344) + doff, src0 + (size_t)t * CC);
        CPA_COMMIT();
    };

#pragma unroll
    for (int s = 0; s < 7; s++) issue(s);

    float4 s4 = make_float4(0.f, 0.f, 0.f, 0.f);
    for (int t = 0; t < TT; t++) {
        asm volatile("cp.async.wait_group 6;" ::: "memory");
        __syncthreads();
        int tn = t + 7; if (tn > TT - 1) tn = TT - 1;
        issue(tn);

        const float* st = ring + (t & 7) * 336;
        float4 dv  = ((const float4*)(st))[cg];
        float4 kv  = ((const float4*)(st + 64))[cg];
        float4 kkv = ((const float4*)(st + 128))[cg];
        float4 rv  = ((const float4*)(st + 192))[cg];
        float4 av  = ((const float4*)(st + 256))[cg];
        float  vi  = st[320 + il];

        float sa = s4.x * kkv.x + s4.y * kkv.y + s4.z * kkv.z + s4.w * kkv.w;
        sa += __shfl_xor_sync(0xffffffffu, sa, 1);
        sa += __shfl_xor_sync(0xffffffffu, sa, 2);
        sa += __shfl_xor_sync(0xffffffffu, sa, 4);
        sa += __shfl_xor_sync(0xffffffffu, sa, 8);
        sa = -sa;

        s4.x = fmaf(vi, kv.x, fmaf(sa, kkv.x * av.x, s4.x * dv.x));
        s4.y = fmaf(vi, kv.y, fmaf(sa, kkv.y * av.y, s4.y * dv.y));
        s4.z = fmaf(vi, kv.z, fmaf(sa, kkv.z * av.z, s4.z * dv.z));
        s4.w = fmaf(vi, kv.w, fmaf(sa, kkv.w * av.w, s4.w * dv.w));

        float o = s4.x * rv.x + s4.y * rv.y + s4.z * rv.z + s4.w * rv.w;
        o += __shfl_xor_sync(0xffffffffu, o, 1);
        o += __shfl_xor_sync(0xffffffffu, o, 2);
        o += __shfl_xor_sync(0xffffffffu, o, 4);
        o += __shfl_xor_sync(0xffffffffu, o, 8);
        if (cg == 0) Y[(size_t)t * CC + rowidx] = o;
    }
}

// ---------------- groupnorm + bonus + gate -> bf16 hi/lo ----------------
__global__ __launch_bounds__(512) void k_gn(
    const float* __restrict__ Yin, const float* __restrict__ R,
    const float* __restrict__ K,   const float* __restrict__ V,
    const float* __restrict__ G,   const float* __restrict__ faaaa,
    const float* __restrict__ lnw, const float* __restrict__ lnb,
    __nv_bfloat16* __restrict__ ymhi, __nv_bfloat16* __restrict__ ymlo) {
    const int t = blockIdx.x, tid = threadIdx.x;
    const int c = tid * 4;
    const size_t idx = (size_t)t * CC + c;
    float4 y  = *(const float4*)&Yin[idx];
    float4 r4 = *(const float4*)&R[idx];
    float4 k4 = *(const float4*)&K[idx];
    float4 v4 = *(const float4*)&V[idx];
    float4 g4 = *(const float4*)&G[idx];
    float4 f4 = *(const float4*)&faaaa[c];
    float4 w4 = *(const float4*)&lnw[c];
    float4 b4 = *(const float4*)&lnb[c];

    float s1 = y.x + y.y + y.z + y.w;
    float s2 = y.x*y.x + y.y*y.y + y.z*y.z + y.w*y.w;
    float s3 = r4.x*k4.x*f4.x + r4.y*k4.y*f4.y + r4.z*k4.z*f4.z + r4.w*k4.w*f4.w;
#pragma unroll
    for (int m = 1; m <= 8; m <<= 1) {
        s1 += __shfl_xor_sync(0xffffffffu, s1, m);
        s2 += __shfl_xor_sync(0xffffffffu, s2, m);
        s3 += __shfl_xor_sync(0xffffffffu, s3, m);
    }
    float mu  = s1 * (1.f / 64.f);
    float var = s2 * (1.f / 64.f) - mu * mu;
    float rs  = rsqrtf(var + EPSGN);
    float o[4];
    o[0] = (fmaf((y.x - mu) * rs, w4.x, b4.x) + s3 * v4.x) * g4.x;
    o[1] = (fmaf((y.y - mu) * rs, w4.y, b4.y) + s3 * v4.y) * g4.y;
    o[2] = (fmaf((y.z - mu) * rs, w4.z, b4.z) + s3 * v4.z) * g4.z;
    o[3] = (fmaf((y.w - mu) * rs, w4.w, b4.w) + s3 * v4.w) * g4.w;
    __nv_bfloat16 hh[4], ll[4];
#pragma unroll
    for (int q = 0; q < 4; q++) {
        hh[q] = __float2bfloat16(o[q]);
        ll[q] = __float2bfloat16(o[q] - __bfloat162float(hh[q]));
    }
    *(uint2*)&ymhi[idx] = *(uint2*)hh;
    *(uint2*)&ymlo[idx] = *(uint2*)ll;
}

// ---------------------------------------------------------------------------
extern "C" void kernel_launch(void* const* d_in, const int* in_sizes, int n_in,
                              void* d_out, int out_size) {
    const float* x      = (const float*)d_in[0];
    const float* Wq     = (const float*)d_in[1];
    const float* Wk     = (const float*)d_in[2];
    const float* Wv     = (const float*)d_in[3];
    const float* Wo     = (const float*)d_in[4];
    const float* tmx    = (const float*)d_in[5];
    const float* tmrg   = (const float*)d_in[6];
    const float* tmwa   = (const float*)d_in[7];
    const float* tmk    = (const float*)d_in[8];
    const float* tmv    = (const float*)d_in[9];
    const float* maa_w1 = (const float*)d_in[10];
    const float* maa_w2 = (const float*)d_in[11];
    const float* tdecay = (const float*)d_in[12];
    const float* dw1    = (const float*)d_in[13];
    const float* dw2    = (const float*)d_in[14];
    const float* taaaaa = (const float*)d_in[15];
    const float* aaa_w1 = (const float*)d_in[16];
    const float* aaa_w2 = (const float*)d_in[17];
    const float* kkk_w1 = (const float*)d_in[18];
    const float* kkk_w2 = (const float*)d_in[19];
    const float* gate_w1 = (const float*)d_in[20];
    const float* gate_w2 = (const float*)d_in[21];
    const float* tmisca = (const float*)d_in[22];
    const float* ma_w1  = (const float*)d_in[23];
    const float* ma_w2  = (const float*)d_in[24];
    const float* tmisck = (const float*)d_in[25];
    const float* mk_w1  = (const float*)d_in[26];
    const float* mk_w2  = (const float*)d_in[27];
    const float* faaaa  = (const float*)d_in[28];
    const float* lnw    = (const float*)d_in[29];
    const float* lnb    = (const float*)d_in[30];
    float* out = (float*)d_out;

    float* S = nullptr;
    cudaGetSymbolAddress((void**)&S, g_scratch);
    __nv_bfloat16* BF = nullptr;
    cudaGetSymbolAddress((void**)&BF, g_bf);

    float* dxp  = S + O_DXP;  float* xxx  = S + O_XXX;
    float* xrg  = S + O_XRG;  float* xwa  = S + O_XWA;
    float* xk   = S + O_XK;   float* xv   = S + O_XV;
    float* R    = S + O_R;    float* Kraw = S + O_KRAW;
    float* V    = S + O_V;    float* Dec  = S + O_DEC;
    float* A    = S + O_A;    float* KK   = S + O_KK;
    float* K    = S + O_K;    float* G    = S + O_G;
    float* Y    = S + O_Y;
    float* hmix = S + O_HMIX; float* gh   = S + O_GH;
    float* hd   = S + O_HD;   float* haaa = S + O_HAAA;
    float* hma  = S + O_HMA;  float* hmk  = S + O_HMK;
    float* hkkk = S + O_HKKK;

    __nv_bfloat16* Wbuf[4][2];
    for (int i = 0; i < 4; i++) {
        Wbuf[i][0] = BF + (size_t)i * 2 * CC * CC;
        Wbuf[i][1] = Wbuf[i][0] + (size_t)CC * CC;
    }
    __nv_bfloat16* Abase = BF + 8ull * CC * CC;
    __nv_bfloat16* ArgH = Abase + 0ull * TC; __nv_bfloat16* ArgL = Abase + 1ull * TC;
    __nv_bfloat16* AkH  = Abase + 2ull * TC; __nv_bfloat16* AkL  = Abase + 3ull * TC;
    __nv_bfloat16* AvH  = Abase + 4ull * TC; __nv_bfloat16* AvL  = Abase + 5ull * TC;
    __nv_bfloat16* AyH  = Abase + 6ull * TC; __nv_bfloat16* AyL  = Abase + 7ull * TC;

    cudaFuncSetAttribute(k_bigmm, cudaFuncAttributeMaxDynamicSharedMemorySize, GM_SMEM);
    const int PS128 = 2 * (64 * 128 + 512) * 4;
    const int PS64  = 2 * (64 * 64  + 512) * 4;
    const int PS32  = 2 * (64 * 32  + 512) * 4;
    cudaFuncSetAttribute((const void*)k_proj<128,128,1,0>, cudaFuncAttributeMaxDynamicSharedMemorySize, PS128);
    cudaFuncSetAttribute((const void*)k_proj<64,64,1,0>,   cudaFuncAttributeMaxDynamicSharedMemorySize, PS64);
    cudaFuncSetAttribute((const void*)k_proj<32,16,0,0>,   cudaFuncAttributeMaxDynamicSharedMemorySize, PS32);
    cudaFuncSetAttribute((const void*)k_proj<32,16,0,1>,   cudaFuncAttributeMaxDynamicSharedMemorySize, PS32);

    dim3 mg(CC / 128, TT / 128);

    // 1: tokshift + all weight preps
    k_init<<<8192 + 16384, 256>>>(x, tmx, dxp, xxx, Wq, Wk, Wv, Wo, BF);
    // 2
    k_proj<128,128,1,0><<<TT / 8, 256, PS128>>>(xxx, maa_w1, maa_w1, hmix, hmix);
    // 3 (also emits bf16 xrg/xk/xv)
    k_mix_apply<<<dim3(CC / 128, TT / 8, 4), 128>>>(x, dxp, hmix, maa_w2,
                                                    tmrg, tmwa, tmk, tmv,
                                                    xrg, xwa, xk, xv,
                                                    ArgH, ArgL, AkH, AkL, AvH, AvL);
    // 4 (ncu capture slot)
    k_bigmm<<<mg, 256, GM_SMEM>>>(ArgH, ArgL, Wbuf[0][0], Wbuf[0][1], R);
    k_bigmm<<<mg, 256, GM_SMEM>>>(AkH, AkL, Wbuf[1][0], Wbuf[1][1], Kraw);
    k_bigmm<<<mg, 256, GM_SMEM>>>(AvH, AvL, Wbuf[2][0], Wbuf[2][1], V);

    k_proj<128,128,1,0><<<TT / 8, 256, PS128>>>(xrg, gate_w1, gate_w1, gh, gh);
    k_proj<64,64,1,0>  <<<TT / 8, 256, PS64 >>>(xwa, dw1, dw1, hd, hd);
    k_proj<32,16,0,0>  <<<TT / 8, 256, PS32 >>>(xwa, aaa_w1, ma_w1, haaa, hma);
    k_proj<32,16,0,1>  <<<TT / 8, 256, PS32 >>>(xk,  mk_w1, kkk_w1, hmk, hkkk);

    k_stage2<<<TT / 8, 256>>>(Kraw, hd, haaa, hma, hmk, hkkk, gh,
                              tdecay, dw2, taaaaa, aaa_w2, tmisca, ma_w2,
                              tmisck, mk_w2, kkk_w2, gate_w2,
                              Dec, A, KK, K, G);
    k_kknorm<<<TT, 256>>>(KK);
    k_wkv<<<dim3(HH, 4), 256>>>(R, Dec, K, KK, A, V, Y);
    k_gn<<<TT, 512>>>(Y, R, K, V, G, faaaa, lnw, lnb, AyH, AyL);
    k_bigmm<<<mg, 256, GM_SMEM>>>(AyH, AyL, Wbuf[3][0], Wbuf[3][1], out);
}